// round 9
// baseline (speedup 1.0000x reference)
#include <cuda_runtime.h>
#include <cuda_bf16.h>
#include <math.h>
#include <stdint.h>

#define NN 20000
#define EE 640000
#define GG 100
#define HH 128
#define TILE_M 128
#define NTILES ((NN + TILE_M - 1) / TILE_M)   // 157
#define P 136                                  // pitch in bf16 (272B rows)
#define SZT (128 * P)
#define SMEM_MMA (4 * SZT * 2)                 // Xh|Xl|Wh|Wl = 139264 B

// ---------------- scratch (device globals; no allocation allowed) ----------------
__device__ float g_node[NN * HH];   // node buffer A
__device__ float g_h[NN * HH];      // node buffer B (ping-pong)
__device__ float g_ae[NN * HH];
__device__ float g_TB[GG * HH];
__device__ float g_v[HH];
__device__ float g_c[HH];
__device__ int   g_offs[GG + 1];
__device__ int   g_gid[NN];
__device__ int   g_cnt[NN];
__device__ int   g_rowptr[NN + 1];
__device__ int   g_cursor[NN];
__device__ int2  g_ef[EE];
// pre-split weights: [matrix][hi/lo][n*P+k], transposed [n][k]
// 0: atomW1(k=100) 1: atomW2 2: nodeA 3: nodeC 4: nodeW2 5..10: conv{w1,w2}x3
__device__ __align__(16) __nv_bfloat16 g_wsp[11][2][SZT];

// ---------------- helpers ---------------------------------------------------------
__device__ __forceinline__ uint32_t smem_u32(const void* p) {
    uint32_t a;
    asm("{ .reg .u64 t; cvta.to.shared.u64 t, %1; cvt.u32.u64 %0, t; }" : "=r"(a) : "l"(p));
    return a;
}
__device__ __forceinline__ void ldsm4(uint32_t r[4], uint32_t addr) {
    asm volatile("ldmatrix.sync.aligned.m8n8.x4.shared.b16 {%0,%1,%2,%3},[%4];"
                 : "=r"(r[0]), "=r"(r[1]), "=r"(r[2]), "=r"(r[3]) : "r"(addr));
}
__device__ __forceinline__ void mma16816(float c[4], const uint32_t a[4], const uint32_t b[2]) {
    asm volatile("mma.sync.aligned.m16n8k16.row.col.f32.bf16.bf16.f32 "
                 "{%0,%1,%2,%3},{%4,%5,%6,%7},{%8,%9},{%0,%1,%2,%3};"
                 : "+f"(c[0]), "+f"(c[1]), "+f"(c[2]), "+f"(c[3])
                 : "r"(a[0]), "r"(a[1]), "r"(a[2]), "r"(a[3]), "r"(b[0]), "r"(b[1]));
}
__device__ __forceinline__ void split_bf(float x, __nv_bfloat16& h, __nv_bfloat16& l) {
    h = __float2bfloat16(x);
    l = __float2bfloat16(x - __bfloat162float(h));
}
__device__ __forceinline__ void cpa16(uint32_t dst, const void* src) {
    asm volatile("cp.async.cg.shared.global [%0],[%1],16;" :: "r"(dst), "l"(src));
}
#define CP_COMMIT() asm volatile("cp.async.commit_group;" ::: "memory")
#define CP_WAIT0()  asm volatile("cp.async.wait_group 0;" ::: "memory")

// ---------------- software-pipelined fused 3-product MMA stage --------------------
template <int KS>
__device__ __forceinline__ void mma_stage(const __nv_bfloat16* __restrict__ Xh,
                                          const __nv_bfloat16* __restrict__ Xl,
                                          const __nv_bfloat16* __restrict__ Wh,
                                          const __nv_bfloat16* __restrict__ Wl,
                                          int rbase, int cbase, int lane,
                                          float acc[2][4][4])
{
    int arow = rbase + (lane & 15);
    int acol = (lane >> 4) << 3;
    int brow = cbase + (lane & 7) + ((lane >> 4) << 3);
    int bcol = ((lane >> 3) & 1) << 3;
    uint32_t ah[2][2][4], al[2][2][4], bh[2][2][4], bl[2][2][4];

#pragma unroll
    for (int mf = 0; mf < 2; mf++) {
        ldsm4(ah[0][mf], smem_u32(Xh + (arow + mf * 16) * P + acol));
        ldsm4(al[0][mf], smem_u32(Xl + (arow + mf * 16) * P + acol));
        ldsm4(bh[0][mf], smem_u32(Wh + (brow + mf * 16) * P + bcol));
        ldsm4(bl[0][mf], smem_u32(Wl + (brow + mf * 16) * P + bcol));
    }
#pragma unroll
    for (int ks = 0; ks < KS; ks++) {
        const int cur = ks & 1, nxt = cur ^ 1;
        if (ks + 1 < KS) {
            int k0 = (ks + 1) * 16;
#pragma unroll
            for (int mf = 0; mf < 2; mf++) {
                ldsm4(ah[nxt][mf], smem_u32(Xh + (arow + mf * 16) * P + k0 + acol));
                ldsm4(al[nxt][mf], smem_u32(Xl + (arow + mf * 16) * P + k0 + acol));
                ldsm4(bh[nxt][mf], smem_u32(Wh + (brow + mf * 16) * P + k0 + bcol));
                ldsm4(bl[nxt][mf], smem_u32(Wl + (brow + mf * 16) * P + k0 + bcol));
            }
        }
#pragma unroll
        for (int mf = 0; mf < 2; mf++)
#pragma unroll
            for (int nf = 0; nf < 4; nf++) {
                const uint32_t* ph = &bh[cur][nf >> 1][(nf & 1) * 2];
                const uint32_t* pl = &bl[cur][nf >> 1][(nf & 1) * 2];
                mma16816(acc[mf][nf], ah[cur][mf], ph);
                mma16816(acc[mf][nf], ah[cur][mf], pl);
                mma16816(acc[mf][nf], al[cur][mf], ph);
            }
    }
}

__device__ __forceinline__ void acc_zero(float acc[2][4][4])
{
#pragma unroll
    for (int mf = 0; mf < 2; mf++)
#pragma unroll
        for (int nf = 0; nf < 4; nf++)
#pragma unroll
            for (int j = 0; j < 4; j++) acc[mf][nf][j] = 0.f;
}

__device__ __forceinline__ void copy_w_async(int m, __nv_bfloat16* Wh, __nv_bfloat16* Wl, int tid)
{
    uint32_t dh = smem_u32(Wh), dl = smem_u32(Wl);
    const char* sh = (const char*)g_wsp[m][0];
    const char* sl = (const char*)g_wsp[m][1];
    for (int i = tid; i < (SZT * 2) / 16; i += 512) {
        cpa16(dh + i * 16, sh + i * 16);
        cpa16(dl + i * 16, sl + i * 16);
    }
}

// vectorized X split, stride 128
__device__ __forceinline__ void load_x128v(const float* __restrict__ X, int row0,
                                           __nv_bfloat16* Xh, __nv_bfloat16* Xl, int tid)
{
    for (int i = tid; i < 128 * 32; i += 512) {
        int r = i >> 5, q = i & 31;
        int row = row0 + r;
        float4 v = (row < NN) ? *(const float4*)(X + (size_t)row * 128 + q * 4)
                              : make_float4(0.f, 0.f, 0.f, 0.f);
        __nv_bfloat16 h0, l0, h1, l1, h2, l2, h3, l3;
        split_bf(v.x, h0, l0); split_bf(v.y, h1, l1);
        split_bf(v.z, h2, l2); split_bf(v.w, h3, l3);
        int o = r * P + q * 4;
        *(__nv_bfloat162*)(Xh + o)     = __nv_bfloat162{h0, h1};
        *(__nv_bfloat162*)(Xh + o + 2) = __nv_bfloat162{h2, h3};
        *(__nv_bfloat162*)(Xl + o)     = __nv_bfloat162{l0, l1};
        *(__nv_bfloat162*)(Xl + o + 2) = __nv_bfloat162{l2, l3};
    }
}

// vectorized X split, stride 100 padded to 112 (atom_types)
__device__ __forceinline__ void load_xatomv(const float* __restrict__ X, int row0,
                                            __nv_bfloat16* Xh, __nv_bfloat16* Xl, int tid)
{
    for (int i = tid; i < 128 * 28; i += 512) {
        int r = i / 28, q = i - r * 28;
        int row = row0 + r;
        float4 v = (q < 25 && row < NN) ? *(const float4*)(X + (size_t)row * 100 + q * 4)
                                        : make_float4(0.f, 0.f, 0.f, 0.f);
        __nv_bfloat16 h0, l0, h1, l1, h2, l2, h3, l3;
        split_bf(v.x, h0, l0); split_bf(v.y, h1, l1);
        split_bf(v.z, h2, l2); split_bf(v.w, h3, l3);
        int o = r * P + q * 4;
        *(__nv_bfloat162*)(Xh + o)     = __nv_bfloat162{h0, h1};
        *(__nv_bfloat162*)(Xh + o + 2) = __nv_bfloat162{h2, h3};
        *(__nv_bfloat162*)(Xl + o)     = __nv_bfloat162{l0, l1};
        *(__nv_bfloat162*)(Xl + o + 2) = __nv_bfloat162{l2, l3};
    }
}

// stage-1 epilogue: acc + bias (or per-row TB) -> relu -> split -> smem X tiles
__device__ __forceinline__ void epi_mid(float acc[2][4][4], const float* __restrict__ bias,
                                        bool use_tb, int row0,
                                        __nv_bfloat16* Xh, __nv_bfloat16* Xl,
                                        int rbase, int cbase, int lane)
{
    int gid = lane >> 2, tig = lane & 3;
#pragma unroll
    for (int mf = 0; mf < 2; mf++) {
#pragma unroll
        for (int half = 0; half < 2; half++) {
            int rl = rbase + mf * 16 + gid + half * 8;
            const float* add;
            if (use_tb) {
                int row = row0 + rl;
                if (row >= NN) row = NN - 1;
                add = &g_TB[(size_t)g_gid[row] * 128];
            } else {
                add = bias;
            }
#pragma unroll
            for (int nf = 0; nf < 4; nf++) {
                int col = cbase + nf * 8 + tig * 2;
                float v0 = fmaxf(acc[mf][nf][half * 2 + 0] + add[col], 0.f);
                float v1 = fmaxf(acc[mf][nf][half * 2 + 1] + add[col + 1], 0.f);
                __nv_bfloat16 h0, l0, h1, l1;
                split_bf(v0, h0, l0);
                split_bf(v1, h1, l1);
                *(__nv_bfloat162*)(Xh + rl * P + col) = __nv_bfloat162{h0, h1};
                *(__nv_bfloat162*)(Xl + rl * P + col) = __nv_bfloat162{l0, l1};
            }
        }
    }
}

// stage-2 epilogue: + bias, [relu], [+Nin residual], fp32 store to Y
__device__ __forceinline__ void epi_out(float acc[2][4][4], const float* __restrict__ bias,
                                        const float* __restrict__ Nin,
                                        float* __restrict__ Y, int row0,
                                        int rbase, int cbase, int lane, bool relu, bool resid)
{
    int gid = lane >> 2, tig = lane & 3;
#pragma unroll
    for (int mf = 0; mf < 2; mf++) {
#pragma unroll
        for (int half = 0; half < 2; half++) {
            int row = row0 + rbase + mf * 16 + gid + half * 8;
            if (row >= NN) continue;
#pragma unroll
            for (int nf = 0; nf < 4; nf++) {
                int col = cbase + nf * 8 + tig * 2;
                float v0 = acc[mf][nf][half * 2 + 0] + bias[col];
                float v1 = acc[mf][nf][half * 2 + 1] + bias[col + 1];
                if (relu) { v0 = fmaxf(v0, 0.f); v1 = fmaxf(v1, 0.f); }
                if (resid) {
                    float2 nd = *(const float2*)(Nin + (size_t)row * 128 + col);
                    v0 += nd.x; v1 += nd.y;
                }
                *(float2*)(Y + (size_t)row * 128 + col) = make_float2(v0, v1);
            }
        }
    }
}

// ---------------- setup: offsets + rank-1 edge vector + zero counters -------------
__global__ __launch_bounds__(512) void k_setup(const float* __restrict__ ew1, const float* __restrict__ eb1,
                                               const float* __restrict__ ew2, const float* __restrict__ eb2,
                                               const int* __restrict__ num_atoms)
{
    int b = blockIdx.x, t = threadIdx.x;
    // all blocks: zero per-dst counters
    int i = b * 512 + t;
    if (i < NN) g_cnt[i] = 0;
    if (b != 0) return;
    __shared__ int s_na[GG];
    __shared__ int s_off[GG + 1];
    if (t < GG) s_na[t] = num_atoms[t];
    __syncthreads();
    if (t == 0) {
        int o = 0;
        for (int g = 0; g < GG; g++) { s_off[g] = o; o += s_na[g]; }
        s_off[GG] = o;
    }
    __syncthreads();
    if (t <= GG) g_offs[t] = s_off[t];
    if (t < HH) {
        float v = 0.f, c = 0.f;
        for (int j = 0; j < HH; j++) {
            float w = ew1[j];
            if (w > 0.f) {
                float w2 = ew2[j * HH + t];
                v = fmaf(w, w2, v);
                c = fmaf(eb1[j], w2, c);
            }
        }
        g_v[t] = v;
        g_c[t] = c + eb2[t];
    }
}

// ---------------- mega prologue: weights + temb + gid + edge count ----------------
#define MB_W    44                       // 44 weight blocks (4 per matrix)
#define MB_T    (MB_W + GG)              // 144
#define MB_G    (MB_T + 40)              // 184 (gid: 40*512 >= NN)
#define MB_C    (MB_G + 200)             // 384 (count: 200*3200 = 640000)
#define MEGA_GRID MB_C

__global__ __launch_bounds__(512) void k_mega(
    const float* __restrict__ t_in,
    const float* __restrict__ tw1, const float* __restrict__ tb1,
    const float* __restrict__ tw2, const float* __restrict__ tb2,
    const float* __restrict__ fw1, const float* __restrict__ fb1,
    const int* __restrict__ ei,
    const float* __restrict__ w0, const float* __restrict__ w1,
    const float* __restrict__ w2, const float* __restrict__ w3,
    const float* __restrict__ w4, const float* __restrict__ w5,
    const float* __restrict__ w6, const float* __restrict__ w7,
    const float* __restrict__ w8, const float* __restrict__ w9,
    const float* __restrict__ w10)
{
    __shared__ float emb[128];
    __shared__ float mid[512];
    __shared__ float part[512];
    __shared__ float tout[128];
    int b = blockIdx.x, tid = threadIdx.x;

    if (b < MB_W) {
        int m = b >> 2, quarter = b & 3;
        const float* W;
        switch (m) {
            case 0: W = w0; break;  case 1: W = w1; break;  case 2: W = w2; break;
            case 3: W = w3; break;  case 4: W = w4; break;  case 5: W = w5; break;
            case 6: W = w6; break;  case 7: W = w7; break;  case 8: W = w8; break;
            case 9: W = w9; break;  default: W = w10; break;
        }
        int kreal = (m == 0) ? 100 : 128;
        for (int j = quarter * 4096 + tid; j < (quarter + 1) * 4096; j += 512) {
            int n = j >> 7, k = j & 127;
            float x = (k < kreal) ? W[k * 128 + n] : 0.f;
            __nv_bfloat16 h, l;
            split_bf(x, h, l);
            g_wsp[m][0][n * P + k] = h;
            g_wsp[m][1][n * P + k] = l;
        }
    } else if (b < MB_T) {
        // time-embedding MLP + fold through fw1 rows 128..255
        int g = b - MB_W;
        if (tid < 128) {
            float tv = t_in[g];
            int i = tid & 63;
            float freq = expf(-9.2103403719761836f * (float)i / 63.0f);
            float a = tv * freq;
            emb[tid] = (tid < 64) ? sinf(a) : cosf(a);
        }
        __syncthreads();
        {
            int col = tid;
            float a0 = 0.f, a1 = 0.f, a2 = 0.f, a3 = 0.f;
#pragma unroll 8
            for (int j = 0; j < 128; j += 4) {
                a0 = fmaf(emb[j + 0], tw1[(j + 0) * 512 + col], a0);
                a1 = fmaf(emb[j + 1], tw1[(j + 1) * 512 + col], a1);
                a2 = fmaf(emb[j + 2], tw1[(j + 2) * 512 + col], a2);
                a3 = fmaf(emb[j + 3], tw1[(j + 3) * 512 + col], a3);
            }
            mid[col] = fmaxf((a0 + a1) + (a2 + a3) + tb1[col], 0.f);
        }
        __syncthreads();
        {
            int col = tid & 127, chunk = tid >> 7;
            const float* m0 = mid + chunk * 128;
            const float* wp = tw2 + chunk * 128 * 128;
            float a0 = 0.f, a1 = 0.f, a2 = 0.f, a3 = 0.f;
#pragma unroll 8
            for (int j = 0; j < 128; j += 4) {
                a0 = fmaf(m0[j + 0], wp[(j + 0) * 128 + col], a0);
                a1 = fmaf(m0[j + 1], wp[(j + 1) * 128 + col], a1);
                a2 = fmaf(m0[j + 2], wp[(j + 2) * 128 + col], a2);
                a3 = fmaf(m0[j + 3], wp[(j + 3) * 128 + col], a3);
            }
            part[tid] = (a0 + a1) + (a2 + a3);
        }
        __syncthreads();
        if (tid < 128)
            tout[tid] = part[tid] + part[tid + 128] + part[tid + 256] + part[tid + 384] + tb2[tid];
        __syncthreads();
        if (tid < 128) {
            int col = tid;
            float a0 = 0.f, a1 = 0.f, a2 = 0.f, a3 = 0.f;
#pragma unroll 8
            for (int j = 0; j < 128; j += 4) {
                a0 = fmaf(tout[j + 0], fw1[(128 + j + 0) * 128 + col], a0);
                a1 = fmaf(tout[j + 1], fw1[(128 + j + 1) * 128 + col], a1);
                a2 = fmaf(tout[j + 2], fw1[(128 + j + 2) * 128 + col], a2);
                a3 = fmaf(tout[j + 3], fw1[(128 + j + 3) * 128 + col], a3);
            }
            g_TB[g * 128 + col] = (a0 + a1) + (a2 + a3) + fb1[col];
        }
    } else if (b < MB_G) {
        // gid binary search
        int i = (b - MB_T) * 512 + tid;
        if (i < NN) {
            int lo = 0, hi = GG;
            while (hi - lo > 1) {
                int m = (lo + hi) >> 1;
                if (g_offs[m] <= i) lo = m; else hi = m;
            }
            g_gid[i] = lo;
        }
    } else {
        // edge count
        int base = (b - MB_G) * 3200;
        for (int j = tid; j < 3200; j += 512) {
            int e = base + j;
            if (e < EE) atomicAdd(&g_cnt[ei[EE + e]], 1);
        }
    }
}

// ---------------- CSR build ------------------------------------------------------
__global__ void k_scan()
{
    const int CH = 20;
    __shared__ int ssum[1024];
    int t = threadIdx.x;
    int base = t * CH;
    int s = 0;
    for (int k = 0; k < CH; k++) {
        int idx = base + k;
        if (idx < NN) s += g_cnt[idx];
    }
    ssum[t] = s;
    __syncthreads();
    for (int off = 1; off < 1024; off <<= 1) {
        int v = (t >= off) ? ssum[t - off] : 0;
        __syncthreads();
        ssum[t] += v;
        __syncthreads();
    }
    int run = (t > 0) ? ssum[t - 1] : 0;
    for (int k = 0; k < CH; k++) {
        int idx = base + k;
        if (idx < NN) {
            g_rowptr[idx] = run;
            g_cursor[idx] = run;
            run += g_cnt[idx];
        }
    }
    if (t == 0) g_rowptr[NN] = EE;
}

__global__ void k_fill(const int* __restrict__ ei, const float* __restrict__ ed)
{
    int e = blockIdx.x * blockDim.x + threadIdx.x;
    if (e >= EE) return;
    int dst = ei[EE + e];
    int pos = atomicAdd(&g_cursor[dst], 1);
    g_ef[pos] = make_int2(ei[e], __float_as_int(ed[e]));
}

// ---------------- atom_emb = MLP2(atom_types) : 100 -> 128 -> 128 ----------------
__global__ __launch_bounds__(512, 1) void k_atom_t(const float* __restrict__ X,
                                                   const float* __restrict__ b1,
                                                   const float* __restrict__ b2)
{
    extern __shared__ __nv_bfloat16 sm[];
    __nv_bfloat16 *Xh = sm, *Xl = sm + SZT, *Wh = sm + 2 * SZT, *Wl = sm + 3 * SZT;
    int tid = threadIdx.x, wid = tid >> 5, lane = tid & 31;
    int rbase = (wid & 3) * 32, cbase = (wid >> 2) * 32;
    int row0 = blockIdx.x * TILE_M;
    float acc[2][4][4];

    copy_w_async(0, Wh, Wl, tid);
    CP_COMMIT();
    load_xatomv(X, row0, Xh, Xl, tid);
    CP_WAIT0();
    __syncthreads();
    acc_zero(acc);
    mma_stage<7>(Xh, Xl, Wh, Wl, rbase, cbase, lane, acc);
    __syncthreads();
    epi_mid(acc, b1, false, row0, Xh, Xl, rbase, cbase, lane);
    copy_w_async(1, Wh, Wl, tid);
    CP_COMMIT(); CP_WAIT0();
    __syncthreads();
    acc_zero(acc);
    mma_stage<8>(Xh, Xl, Wh, Wl, rbase, cbase, lane, acc);
    epi_out(acc, b2, nullptr, g_ae, row0, rbase, cbase, lane, false, false);
}

// ---------------- node = relu(z@A + ae@C + TB[g]) @ fw2 + fb2 --------------------
__global__ __launch_bounds__(512, 1) void k_node_t(const float* __restrict__ Z,
                                                   const float* __restrict__ fb2)
{
    extern __shared__ __nv_bfloat16 sm[];
    __nv_bfloat16 *Xh = sm, *Xl = sm + SZT, *Wh = sm + 2 * SZT, *Wl = sm + 3 * SZT;
    int tid = threadIdx.x, wid = tid >> 5, lane = tid & 31;
    int rbase = (wid & 3) * 32, cbase = (wid >> 2) * 32;
    int row0 = blockIdx.x * TILE_M;
    float acc[2][4][4];

    copy_w_async(2, Wh, Wl, tid);
    CP_COMMIT();
    load_x128v(Z, row0, Xh, Xl, tid);
    CP_WAIT0();
    __syncthreads();
    acc_zero(acc);
    mma_stage<8>(Xh, Xl, Wh, Wl, rbase, cbase, lane, acc);
    __syncthreads();
    copy_w_async(3, Wh, Wl, tid);
    CP_COMMIT();
    load_x128v(g_ae, row0, Xh, Xl, tid);
    CP_WAIT0();
    __syncthreads();
    mma_stage<8>(Xh, Xl, Wh, Wl, rbase, cbase, lane, acc);
    __syncthreads();
    epi_mid(acc, nullptr, true, row0, Xh, Xl, rbase, cbase, lane);
    copy_w_async(4, Wh, Wl, tid);
    CP_COMMIT(); CP_WAIT0();
    __syncthreads();
    acc_zero(acc);
    mma_stage<8>(Xh, Xl, Wh, Wl, rbase, cbase, lane, acc);
    epi_out(acc, fb2, nullptr, g_node, row0, rbase, cbase, lane, false, false);
}

// ---------------- fused GINE layer: agg + MLP2 + residual -------------------------
__device__ __forceinline__ void agg_step(float4& acc, const float4& x, float d,
                                         const float4& v4, const float4& c4)
{
    acc.x += fmaxf(fmaf(d, v4.x, x.x + c4.x), 0.f);
    acc.y += fmaxf(fmaf(d, v4.y, x.y + c4.y), 0.f);
    acc.z += fmaxf(fmaf(d, v4.z, x.z + c4.z), 0.f);
    acc.w += fmaxf(fmaf(d, v4.w, x.w + c4.w), 0.f);
}

__global__ __launch_bounds__(512, 1) void k_conv_t(int wsel,
                                                   const float* __restrict__ b1,
                                                   const float* __restrict__ b2,
                                                   const float* __restrict__ Nin,
                                                   float* __restrict__ Yout, int relu_out)
{
    extern __shared__ __nv_bfloat16 sm[];
    __nv_bfloat16 *Xh = sm, *Xl = sm + SZT, *Wh = sm + 2 * SZT, *Wl = sm + 3 * SZT;
    int tid = threadIdx.x, wid = tid >> 5, lane = tid & 31;
    int rbase = (wid & 3) * 32, cbase = (wid >> 2) * 32;
    int row0 = blockIdx.x * TILE_M;
    float acc[2][4][4];

    copy_w_async(wsel, Wh, Wl, tid);
    CP_COMMIT();

    // aggregation phase: warp per dst row, write relu-sum split into X tiles
    {
        float4 v4 = *(const float4*)(g_v + lane * 4);
        float4 c4 = *(const float4*)(g_c + lane * 4);
        for (int r = wid; r < 128; r += 16) {
            int row = row0 + r;
            float4 a = make_float4(0.f, 0.f, 0.f, 0.f);
            if (row < NN) {
                a = *(const float4*)(Nin + (size_t)row * 128 + lane * 4);
                int e = g_rowptr[row], end = g_rowptr[row + 1];
                for (; e + 4 <= end; e += 4) {
                    int2 p0 = g_ef[e], p1 = g_ef[e + 1], p2 = g_ef[e + 2], p3 = g_ef[e + 3];
                    float4 x0 = *(const float4*)(Nin + (size_t)p0.x * 128 + lane * 4);
                    float4 x1 = *(const float4*)(Nin + (size_t)p1.x * 128 + lane * 4);
                    float4 x2 = *(const float4*)(Nin + (size_t)p2.x * 128 + lane * 4);
                    float4 x3 = *(const float4*)(Nin + (size_t)p3.x * 128 + lane * 4);
                    agg_step(a, x0, __int_as_float(p0.y), v4, c4);
                    agg_step(a, x1, __int_as_float(p1.y), v4, c4);
                    agg_step(a, x2, __int_as_float(p2.y), v4, c4);
                    agg_step(a, x3, __int_as_float(p3.y), v4, c4);
                }
                for (; e < end; e++) {
                    int2 p = g_ef[e];
                    float4 x = *(const float4*)(Nin + (size_t)p.x * 128 + lane * 4);
                    agg_step(a, x, __int_as_float(p.y), v4, c4);
                }
            }
            __nv_bfloat16 h0, l0, h1, l1, h2, l2, h3, l3;
            split_bf(a.x, h0, l0); split_bf(a.y, h1, l1);
            split_bf(a.z, h2, l2); split_bf(a.w, h3, l3);
            int o = r * P + lane * 4;
            *(__nv_bfloat162*)(Xh + o)     = __nv_bfloat162{h0, h1};
            *(__nv_bfloat162*)(Xh + o + 2) = __nv_bfloat162{h2, h3};
            *(__nv_bfloat162*)(Xl + o)     = __nv_bfloat162{l0, l1};
            *(__nv_bfloat162*)(Xl + o + 2) = __nv_bfloat162{l2, l3};
        }
    }
    CP_WAIT0();
    __syncthreads();
    acc_zero(acc);
    mma_stage<8>(Xh, Xl, Wh, Wl, rbase, cbase, lane, acc);
    __syncthreads();
    epi_mid(acc, b1, false, row0, Xh, Xl, rbase, cbase, lane);
    copy_w_async(wsel + 1, Wh, Wl, tid);
    CP_COMMIT(); CP_WAIT0();
    __syncthreads();
    acc_zero(acc);
    mma_stage<8>(Xh, Xl, Wh, Wl, rbase, cbase, lane, acc);
    epi_out(acc, b2, Nin, Yout, row0, rbase, cbase, lane, relu_out != 0, true);
}

// ---------------- launch ---------------------------------------------------------
extern "C" void kernel_launch(void* const* d_in, const int* in_sizes, int n_in,
                              void* d_out, int out_size)
{
    const float* z   = (const float*)d_in[0];
    const float* t   = (const float*)d_in[1];
    const float* at  = (const float*)d_in[2];
    const float* ed  = (const float*)d_in[3];
    const int*   ei  = (const int*)d_in[4];
    const int*   na  = (const int*)d_in[5];
    const float* nw1 = (const float*)d_in[6];
    const float* nb1 = (const float*)d_in[7];
    const float* nw2 = (const float*)d_in[8];
    const float* nb2 = (const float*)d_in[9];
    const float* tw1 = (const float*)d_in[10];
    const float* tb1 = (const float*)d_in[11];
    const float* tw2 = (const float*)d_in[12];
    const float* tb2 = (const float*)d_in[13];
    const float* ew1 = (const float*)d_in[14];
    const float* eb1 = (const float*)d_in[15];
    const float* ew2 = (const float*)d_in[16];
    const float* eb2 = (const float*)d_in[17];
    const float* fw1 = (const float*)d_in[18];
    const float* fb1 = (const float*)d_in[19];
    const float* fw2 = (const float*)d_in[20];
    const float* fb2 = (const float*)d_in[21];
    const float* cw1 = (const float*)d_in[22];
    const float* cb1 = (const float*)d_in[23];
    const float* cw2 = (const float*)d_in[24];
    const float* cb2 = (const float*)d_in[25];
    float* out = (float*)d_out;

    cudaFuncSetAttribute(k_atom_t, cudaFuncAttributeMaxDynamicSharedMemorySize, SMEM_MMA);
    cudaFuncSetAttribute(k_node_t, cudaFuncAttributeMaxDynamicSharedMemorySize, SMEM_MMA);
    cudaFuncSetAttribute(k_conv_t, cudaFuncAttributeMaxDynamicSharedMemorySize, SMEM_MMA);

    k_setup<<<(NN + 511) / 512, 512>>>(ew1, eb1, ew2, eb2, na);
    k_mega<<<MEGA_GRID, 512>>>(t, tw1, tb1, tw2, tb2, fw1, fb1, ei,
                               nw1, nw2, fw1, fw1 + 256 * 128, fw2,
                               cw1, cw2, cw1 + 16384, cw2 + 16384,
                               cw1 + 2 * 16384, cw2 + 2 * 16384);
    k_scan<<<1, 1024>>>();
    k_fill<<<(EE + 511) / 512, 512>>>(ei, ed);
    k_atom_t<<<NTILES, 512, SMEM_MMA>>>(at, nb1, nb2);
    k_node_t<<<NTILES, 512, SMEM_MMA>>>(z, fb2);

    // ping-pong node buffers: g_node -> g_h -> g_node -> out
    float *bufA, *bufB;
    cudaGetSymbolAddress((void**)&bufA, g_node);
    cudaGetSymbolAddress((void**)&bufB, g_h);
    const float* Nin[3]  = { bufA, bufB, bufA };
    float*       Yout[3] = { bufB, bufA, out };
    for (int i = 0; i < 3; i++) {
        k_conv_t<<<NTILES, 512, SMEM_MMA>>>(5 + i * 2, cb1 + i * 128, cb2 + i * 128,
                                            Nin[i], Yout[i], (i < 2) ? 1 : 0);
    }
}

// round 10
// speedup vs baseline: 1.3161x; 1.3161x over previous
#include <cuda_runtime.h>
#include <cuda_bf16.h>
#include <math.h>
#include <stdint.h>

#define NN 20000
#define EE 640000
#define GG 100
#define HH 128
#define TILE_M 128
#define NTILES ((NN + TILE_M - 1) / TILE_M)   // 157
#define P 136                                  // pitch in bf16 (272B rows)
#define SZT (128 * P)
#define SMEM_MMA (4 * SZT * 2)                 // Xh|Xl|Wh|Wl = 139264 B

// ---------------- scratch (device globals; no allocation allowed) ----------------
__device__ float g_node[NN * HH];
__device__ float g_h[NN * HH];
__device__ float g_ae[NN * HH];
__device__ float g_TB[GG * HH];
__device__ float g_v[HH];
__device__ float g_c[HH];
__device__ int   g_offs[GG + 1];
__device__ int   g_gid[NN];
__device__ int   g_cnt[NN];
__device__ int   g_rowptr[NN + 1];
__device__ int   g_cursor[NN];
__device__ int2  g_ef[EE];
// pre-split weights: [matrix][hi/lo][n*P+k], transposed [n][k]
// 0: atomW1(k=100) 1: atomW2 2: nodeA 3: nodeC 4: nodeW2 5..10: conv{w1,w2}x3
__device__ __align__(16) __nv_bfloat16 g_wsp[11][2][SZT];

// ---------------- helpers ---------------------------------------------------------
__device__ __forceinline__ uint32_t smem_u32(const void* p) {
    uint32_t a;
    asm("{ .reg .u64 t; cvta.to.shared.u64 t, %1; cvt.u32.u64 %0, t; }" : "=r"(a) : "l"(p));
    return a;
}
__device__ __forceinline__ void ldsm4(uint32_t r[4], uint32_t addr) {
    asm volatile("ldmatrix.sync.aligned.m8n8.x4.shared.b16 {%0,%1,%2,%3},[%4];"
                 : "=r"(r[0]), "=r"(r[1]), "=r"(r[2]), "=r"(r[3]) : "r"(addr));
}
__device__ __forceinline__ void mma16816(float c[4], const uint32_t a[4], const uint32_t b[2]) {
    asm volatile("mma.sync.aligned.m16n8k16.row.col.f32.bf16.bf16.f32 "
                 "{%0,%1,%2,%3},{%4,%5,%6,%7},{%8,%9},{%0,%1,%2,%3};"
                 : "+f"(c[0]), "+f"(c[1]), "+f"(c[2]), "+f"(c[3])
                 : "r"(a[0]), "r"(a[1]), "r"(a[2]), "r"(a[3]), "r"(b[0]), "r"(b[1]));
}
__device__ __forceinline__ void split_bf(float x, __nv_bfloat16& h, __nv_bfloat16& l) {
    h = __float2bfloat16(x);
    l = __float2bfloat16(x - __bfloat162float(h));
}
__device__ __forceinline__ void cpa16(uint32_t dst, const void* src) {
    asm volatile("cp.async.cg.shared.global [%0],[%1],16;" :: "r"(dst), "l"(src));
}
#define CP_COMMIT() asm volatile("cp.async.commit_group;" ::: "memory")
#define CP_WAIT0()  asm volatile("cp.async.wait_group 0;" ::: "memory")

// ---------------- software-pipelined fused 3-product MMA stage --------------------
template <int KS>
__device__ __forceinline__ void mma_stage(const __nv_bfloat16* __restrict__ Xh,
                                          const __nv_bfloat16* __restrict__ Xl,
                                          const __nv_bfloat16* __restrict__ Wh,
                                          const __nv_bfloat16* __restrict__ Wl,
                                          int rbase, int cbase, int lane,
                                          float acc[2][4][4])
{
    int arow = rbase + (lane & 15);
    int acol = (lane >> 4) << 3;
    int brow = cbase + (lane & 7) + ((lane >> 4) << 3);
    int bcol = ((lane >> 3) & 1) << 3;
    uint32_t ah[2][2][4], al[2][2][4], bh[2][2][4], bl[2][2][4];

#pragma unroll
    for (int mf = 0; mf < 2; mf++) {
        ldsm4(ah[0][mf], smem_u32(Xh + (arow + mf * 16) * P + acol));
        ldsm4(al[0][mf], smem_u32(Xl + (arow + mf * 16) * P + acol));
        ldsm4(bh[0][mf], smem_u32(Wh + (brow + mf * 16) * P + bcol));
        ldsm4(bl[0][mf], smem_u32(Wl + (brow + mf * 16) * P + bcol));
    }
#pragma unroll
    for (int ks = 0; ks < KS; ks++) {
        const int cur = ks & 1, nxt = cur ^ 1;
        if (ks + 1 < KS) {
            int k0 = (ks + 1) * 16;
#pragma unroll
            for (int mf = 0; mf < 2; mf++) {
                ldsm4(ah[nxt][mf], smem_u32(Xh + (arow + mf * 16) * P + k0 + acol));
                ldsm4(al[nxt][mf], smem_u32(Xl + (arow + mf * 16) * P + k0 + acol));
                ldsm4(bh[nxt][mf], smem_u32(Wh + (brow + mf * 16) * P + k0 + bcol));
                ldsm4(bl[nxt][mf], smem_u32(Wl + (brow + mf * 16) * P + k0 + bcol));
            }
        }
#pragma unroll
        for (int mf = 0; mf < 2; mf++)
#pragma unroll
            for (int nf = 0; nf < 4; nf++) {
                const uint32_t* ph = &bh[cur][nf >> 1][(nf & 1) * 2];
                const uint32_t* pl = &bl[cur][nf >> 1][(nf & 1) * 2];
                mma16816(acc[mf][nf], ah[cur][mf], ph);
                mma16816(acc[mf][nf], ah[cur][mf], pl);
                mma16816(acc[mf][nf], al[cur][mf], ph);
            }
    }
}

__device__ __forceinline__ void acc_zero(float acc[2][4][4])
{
#pragma unroll
    for (int mf = 0; mf < 2; mf++)
#pragma unroll
        for (int nf = 0; nf < 4; nf++)
#pragma unroll
            for (int j = 0; j < 4; j++) acc[mf][nf][j] = 0.f;
}

__device__ __forceinline__ void copy_w_async(int m, __nv_bfloat16* Wh, __nv_bfloat16* Wl, int tid)
{
    uint32_t dh = smem_u32(Wh), dl = smem_u32(Wl);
    const char* sh = (const char*)g_wsp[m][0];
    const char* sl = (const char*)g_wsp[m][1];
    for (int i = tid; i < (SZT * 2) / 16; i += 512) {
        cpa16(dh + i * 16, sh + i * 16);
        cpa16(dl + i * 16, sl + i * 16);
    }
}

// vectorized X split, stride 128
__device__ __forceinline__ void load_x128v(const float* __restrict__ X, int row0,
                                           __nv_bfloat16* Xh, __nv_bfloat16* Xl, int tid)
{
    for (int i = tid; i < 128 * 32; i += 512) {
        int r = i >> 5, q = i & 31;
        int row = row0 + r;
        float4 v = (row < NN) ? *(const float4*)(X + (size_t)row * 128 + q * 4)
                              : make_float4(0.f, 0.f, 0.f, 0.f);
        __nv_bfloat16 h0, l0, h1, l1, h2, l2, h3, l3;
        split_bf(v.x, h0, l0); split_bf(v.y, h1, l1);
        split_bf(v.z, h2, l2); split_bf(v.w, h3, l3);
        int o = r * P + q * 4;
        *(__nv_bfloat162*)(Xh + o)     = __nv_bfloat162{h0, h1};
        *(__nv_bfloat162*)(Xh + o + 2) = __nv_bfloat162{h2, h3};
        *(__nv_bfloat162*)(Xl + o)     = __nv_bfloat162{l0, l1};
        *(__nv_bfloat162*)(Xl + o + 2) = __nv_bfloat162{l2, l3};
    }
}

// vectorized X split, stride 100 padded to 112 (atom_types)
__device__ __forceinline__ void load_xatomv(const float* __restrict__ X, int row0,
                                            __nv_bfloat16* Xh, __nv_bfloat16* Xl, int tid)
{
    for (int i = tid; i < 128 * 28; i += 512) {
        int r = i / 28, q = i - r * 28;
        int row = row0 + r;
        float4 v = (q < 25 && row < NN) ? *(const float4*)(X + (size_t)row * 100 + q * 4)
                                        : make_float4(0.f, 0.f, 0.f, 0.f);
        __nv_bfloat16 h0, l0, h1, l1, h2, l2, h3, l3;
        split_bf(v.x, h0, l0); split_bf(v.y, h1, l1);
        split_bf(v.z, h2, l2); split_bf(v.w, h3, l3);
        int o = r * P + q * 4;
        *(__nv_bfloat162*)(Xh + o)     = __nv_bfloat162{h0, h1};
        *(__nv_bfloat162*)(Xh + o + 2) = __nv_bfloat162{h2, h3};
        *(__nv_bfloat162*)(Xl + o)     = __nv_bfloat162{l0, l1};
        *(__nv_bfloat162*)(Xl + o + 2) = __nv_bfloat162{l2, l3};
    }
}

// stage-1 epilogue: acc + bias (or per-row TB) -> relu -> split -> smem X tiles
__device__ __forceinline__ void epi_mid(float acc[2][4][4], const float* __restrict__ bias,
                                        bool use_tb, int row0,
                                        __nv_bfloat16* Xh, __nv_bfloat16* Xl,
                                        int rbase, int cbase, int lane)
{
    int gid = lane >> 2, tig = lane & 3;
#pragma unroll
    for (int mf = 0; mf < 2; mf++) {
#pragma unroll
        for (int half = 0; half < 2; half++) {
            int rl = rbase + mf * 16 + gid + half * 8;
            const float* add;
            if (use_tb) {
                int row = row0 + rl;
                if (row >= NN) row = NN - 1;
                add = &g_TB[(size_t)g_gid[row] * 128];
            } else {
                add = bias;
            }
#pragma unroll
            for (int nf = 0; nf < 4; nf++) {
                int col = cbase + nf * 8 + tig * 2;
                float v0 = fmaxf(acc[mf][nf][half * 2 + 0] + add[col], 0.f);
                float v1 = fmaxf(acc[mf][nf][half * 2 + 1] + add[col + 1], 0.f);
                __nv_bfloat16 h0, l0, h1, l1;
                split_bf(v0, h0, l0);
                split_bf(v1, h1, l1);
                *(__nv_bfloat162*)(Xh + rl * P + col) = __nv_bfloat162{h0, h1};
                *(__nv_bfloat162*)(Xl + rl * P + col) = __nv_bfloat162{l0, l1};
            }
        }
    }
}

// stage-2 epilogue: + bias, [relu], [+g_node residual], fp32 store
__device__ __forceinline__ void epi_out(float acc[2][4][4], const float* __restrict__ bias,
                                        float* __restrict__ Y, int row0,
                                        int rbase, int cbase, int lane, bool relu, bool resid)
{
    int gid = lane >> 2, tig = lane & 3;
#pragma unroll
    for (int mf = 0; mf < 2; mf++) {
#pragma unroll
        for (int half = 0; half < 2; half++) {
            int row = row0 + rbase + mf * 16 + gid + half * 8;
            if (row >= NN) continue;
#pragma unroll
            for (int nf = 0; nf < 4; nf++) {
                int col = cbase + nf * 8 + tig * 2;
                float v0 = acc[mf][nf][half * 2 + 0] + bias[col];
                float v1 = acc[mf][nf][half * 2 + 1] + bias[col + 1];
                if (relu) { v0 = fmaxf(v0, 0.f); v1 = fmaxf(v1, 0.f); }
                if (resid) {
                    float2 nd = *(const float2*)(g_node + (size_t)row * 128 + col);
                    v0 += nd.x; v1 += nd.y;
                }
                *(float2*)(Y + (size_t)row * 128 + col) = make_float2(v0, v1);
            }
        }
    }
}

// ---------------- setup: offsets + rank-1 edge vector + zero counters -------------
__global__ __launch_bounds__(512) void k_setup(const float* __restrict__ ew1, const float* __restrict__ eb1,
                                               const float* __restrict__ ew2, const float* __restrict__ eb2,
                                               const int* __restrict__ num_atoms)
{
    int b = blockIdx.x, t = threadIdx.x;
    int i = b * 512 + t;
    if (i < NN) g_cnt[i] = 0;
    if (b != 0) return;
    __shared__ int s_na[GG];
    __shared__ int s_off[GG + 1];
    if (t < GG) s_na[t] = num_atoms[t];
    __syncthreads();
    if (t == 0) {
        int o = 0;
        for (int g = 0; g < GG; g++) { s_off[g] = o; o += s_na[g]; }
        s_off[GG] = o;
    }
    __syncthreads();
    if (t <= GG) g_offs[t] = s_off[t];
    if (t < HH) {
        float v = 0.f, c = 0.f;
        for (int j = 0; j < HH; j++) {
            float w = ew1[j];
            if (w > 0.f) {
                float w2 = ew2[j * HH + t];
                v = fmaf(w, w2, v);
                c = fmaf(eb1[j], w2, c);
            }
        }
        g_v[t] = v;
        g_c[t] = c + eb2[t];
    }
}

// ---------------- mega prologue: weights + temb + gid + edge count ----------------
#define MB_W    44
#define MB_T    (MB_W + GG)              // 144
#define MB_G    (MB_T + 40)              // 184
#define MB_C    (MB_G + 200)             // 384
#define MEGA_GRID MB_C

__global__ __launch_bounds__(512) void k_mega(
    const float* __restrict__ t_in,
    const float* __restrict__ tw1, const float* __restrict__ tb1,
    const float* __restrict__ tw2, const float* __restrict__ tb2,
    const float* __restrict__ fw1, const float* __restrict__ fb1,
    const int* __restrict__ ei,
    const float* __restrict__ w0, const float* __restrict__ w1,
    const float* __restrict__ w2, const float* __restrict__ w3,
    const float* __restrict__ w4, const float* __restrict__ w5,
    const float* __restrict__ w6, const float* __restrict__ w7,
    const float* __restrict__ w8, const float* __restrict__ w9,
    const float* __restrict__ w10)
{
    __shared__ float emb[128];
    __shared__ float mid[512];
    __shared__ float part[512];
    __shared__ float tout[128];
    int b = blockIdx.x, tid = threadIdx.x;

    if (b < MB_W) {
        int m = b >> 2, quarter = b & 3;
        const float* W;
        switch (m) {
            case 0: W = w0; break;  case 1: W = w1; break;  case 2: W = w2; break;
            case 3: W = w3; break;  case 4: W = w4; break;  case 5: W = w5; break;
            case 6: W = w6; break;  case 7: W = w7; break;  case 8: W = w8; break;
            case 9: W = w9; break;  default: W = w10; break;
        }
        int kreal = (m == 0) ? 100 : 128;
        for (int j = quarter * 4096 + tid; j < (quarter + 1) * 4096; j += 512) {
            int n = j >> 7, k = j & 127;
            float x = (k < kreal) ? W[k * 128 + n] : 0.f;
            __nv_bfloat16 h, l;
            split_bf(x, h, l);
            g_wsp[m][0][n * P + k] = h;
            g_wsp[m][1][n * P + k] = l;
        }
    } else if (b < MB_T) {
        int g = b - MB_W;
        if (tid < 128) {
            float tv = t_in[g];
            int i = tid & 63;
            float freq = expf(-9.2103403719761836f * (float)i / 63.0f);
            float a = tv * freq;
            emb[tid] = (tid < 64) ? sinf(a) : cosf(a);
        }
        __syncthreads();
        {
            int col = tid;
            float a0 = 0.f, a1 = 0.f, a2 = 0.f, a3 = 0.f;
#pragma unroll 8
            for (int j = 0; j < 128; j += 4) {
                a0 = fmaf(emb[j + 0], tw1[(j + 0) * 512 + col], a0);
                a1 = fmaf(emb[j + 1], tw1[(j + 1) * 512 + col], a1);
                a2 = fmaf(emb[j + 2], tw1[(j + 2) * 512 + col], a2);
                a3 = fmaf(emb[j + 3], tw1[(j + 3) * 512 + col], a3);
            }
            mid[col] = fmaxf((a0 + a1) + (a2 + a3) + tb1[col], 0.f);
        }
        __syncthreads();
        {
            int col = tid & 127, chunk = tid >> 7;
            const float* m0 = mid + chunk * 128;
            const float* wp = tw2 + chunk * 128 * 128;
            float a0 = 0.f, a1 = 0.f, a2 = 0.f, a3 = 0.f;
#pragma unroll 8
            for (int j = 0; j < 128; j += 4) {
                a0 = fmaf(m0[j + 0], wp[(j + 0) * 128 + col], a0);
                a1 = fmaf(m0[j + 1], wp[(j + 1) * 128 + col], a1);
                a2 = fmaf(m0[j + 2], wp[(j + 2) * 128 + col], a2);
                a3 = fmaf(m0[j + 3], wp[(j + 3) * 128 + col], a3);
            }
            part[tid] = (a0 + a1) + (a2 + a3);
        }
        __syncthreads();
        if (tid < 128)
            tout[tid] = part[tid] + part[tid + 128] + part[tid + 256] + part[tid + 384] + tb2[tid];
        __syncthreads();
        if (tid < 128) {
            int col = tid;
            float a0 = 0.f, a1 = 0.f, a2 = 0.f, a3 = 0.f;
#pragma unroll 8
            for (int j = 0; j < 128; j += 4) {
                a0 = fmaf(tout[j + 0], fw1[(128 + j + 0) * 128 + col], a0);
                a1 = fmaf(tout[j + 1], fw1[(128 + j + 1) * 128 + col], a1);
                a2 = fmaf(tout[j + 2], fw1[(128 + j + 2) * 128 + col], a2);
                a3 = fmaf(tout[j + 3], fw1[(128 + j + 3) * 128 + col], a3);
            }
            g_TB[g * 128 + col] = (a0 + a1) + (a2 + a3) + fb1[col];
        }
    } else if (b < MB_G) {
        int i = (b - MB_T) * 512 + tid;
        if (i < NN) {
            int lo = 0, hi = GG;
            while (hi - lo > 1) {
                int m = (lo + hi) >> 1;
                if (g_offs[m] <= i) lo = m; else hi = m;
            }
            g_gid[i] = lo;
        }
    } else {
        int base = (b - MB_G) * 3200;
        for (int j = tid; j < 3200; j += 512) {
            int e = base + j;
            if (e < EE) atomicAdd(&g_cnt[ei[EE + e]], 1);
        }
    }
}

// ---------------- CSR build ------------------------------------------------------
__global__ void k_scan()
{
    const int CH = 20;
    __shared__ int ssum[1024];
    int t = threadIdx.x;
    int base = t * CH;
    int s = 0;
    for (int k = 0; k < CH; k++) {
        int idx = base + k;
        if (idx < NN) s += g_cnt[idx];
    }
    ssum[t] = s;
    __syncthreads();
    for (int off = 1; off < 1024; off <<= 1) {
        int v = (t >= off) ? ssum[t - off] : 0;
        __syncthreads();
        ssum[t] += v;
        __syncthreads();
    }
    int run = (t > 0) ? ssum[t - 1] : 0;
    for (int k = 0; k < CH; k++) {
        int idx = base + k;
        if (idx < NN) {
            g_rowptr[idx] = run;
            g_cursor[idx] = run;
            run += g_cnt[idx];
        }
    }
    if (t == 0) g_rowptr[NN] = EE;
}

__global__ void k_fill(const int* __restrict__ ei, const float* __restrict__ ed)
{
    int e = blockIdx.x * blockDim.x + threadIdx.x;
    if (e >= EE) return;
    int dst = ei[EE + e];
    int pos = atomicAdd(&g_cursor[dst], 1);
    g_ef[pos] = make_int2(ei[e], __float_as_int(ed[e]));
}

// ---------------- atom_emb = MLP2(atom_types) : 100 -> 128 -> 128 ----------------
__global__ __launch_bounds__(512, 1) void k_atom_t(const float* __restrict__ X,
                                                   const float* __restrict__ b1,
                                                   const float* __restrict__ b2)
{
    extern __shared__ __nv_bfloat16 sm[];
    __nv_bfloat16 *Xh = sm, *Xl = sm + SZT, *Wh = sm + 2 * SZT, *Wl = sm + 3 * SZT;
    int tid = threadIdx.x, wid = tid >> 5, lane = tid & 31;
    int rbase = (wid & 3) * 32, cbase = (wid >> 2) * 32;
    int row0 = blockIdx.x * TILE_M;
    float acc[2][4][4];

    copy_w_async(0, Wh, Wl, tid);
    CP_COMMIT();
    load_xatomv(X, row0, Xh, Xl, tid);
    CP_WAIT0();
    __syncthreads();
    acc_zero(acc);
    mma_stage<7>(Xh, Xl, Wh, Wl, rbase, cbase, lane, acc);
    __syncthreads();
    epi_mid(acc, b1, false, row0, Xh, Xl, rbase, cbase, lane);
    copy_w_async(1, Wh, Wl, tid);
    CP_COMMIT(); CP_WAIT0();
    __syncthreads();
    acc_zero(acc);
    mma_stage<8>(Xh, Xl, Wh, Wl, rbase, cbase, lane, acc);
    epi_out(acc, b2, g_ae, row0, rbase, cbase, lane, false, false);
}

// ---------------- node = relu(z@A + ae@C + TB[g]) @ fw2 + fb2 --------------------
__global__ __launch_bounds__(512, 1) void k_node_t(const float* __restrict__ Z,
                                                   const float* __restrict__ fb2)
{
    extern __shared__ __nv_bfloat16 sm[];
    __nv_bfloat16 *Xh = sm, *Xl = sm + SZT, *Wh = sm + 2 * SZT, *Wl = sm + 3 * SZT;
    int tid = threadIdx.x, wid = tid >> 5, lane = tid & 31;
    int rbase = (wid & 3) * 32, cbase = (wid >> 2) * 32;
    int row0 = blockIdx.x * TILE_M;
    float acc[2][4][4];

    copy_w_async(2, Wh, Wl, tid);
    CP_COMMIT();
    load_x128v(Z, row0, Xh, Xl, tid);
    CP_WAIT0();
    __syncthreads();
    acc_zero(acc);
    mma_stage<8>(Xh, Xl, Wh, Wl, rbase, cbase, lane, acc);
    __syncthreads();
    copy_w_async(3, Wh, Wl, tid);
    CP_COMMIT();
    load_x128v(g_ae, row0, Xh, Xl, tid);
    CP_WAIT0();
    __syncthreads();
    mma_stage<8>(Xh, Xl, Wh, Wl, rbase, cbase, lane, acc);
    __syncthreads();
    epi_mid(acc, nullptr, true, row0, Xh, Xl, rbase, cbase, lane);
    copy_w_async(4, Wh, Wl, tid);
    CP_COMMIT(); CP_WAIT0();
    __syncthreads();
    acc_zero(acc);
    mma_stage<8>(Xh, Xl, Wh, Wl, rbase, cbase, lane, acc);
    epi_out(acc, fb2, g_node, row0, rbase, cbase, lane, false, false);
}

// ---------------- conv MLP: Y = [relu](relu(h@W1+b1)@W2+b2) + node ---------------
__global__ __launch_bounds__(512, 1) void k_conv_t(int wsel,
                                                   const float* __restrict__ b1,
                                                   const float* __restrict__ b2,
                                                   float* __restrict__ Yext, int relu_out)
{
    extern __shared__ __nv_bfloat16 sm[];
    __nv_bfloat16 *Xh = sm, *Xl = sm + SZT, *Wh = sm + 2 * SZT, *Wl = sm + 3 * SZT;
    int tid = threadIdx.x, wid = tid >> 5, lane = tid & 31;
    int rbase = (wid & 3) * 32, cbase = (wid >> 2) * 32;
    int row0 = blockIdx.x * TILE_M;
    float* Y = Yext ? Yext : g_node;
    float acc[2][4][4];

    copy_w_async(wsel, Wh, Wl, tid);
    CP_COMMIT();
    load_x128v(g_h, row0, Xh, Xl, tid);
    CP_WAIT0();
    __syncthreads();
    acc_zero(acc);
    mma_stage<8>(Xh, Xl, Wh, Wl, rbase, cbase, lane, acc);
    __syncthreads();
    epi_mid(acc, b1, false, row0, Xh, Xl, rbase, cbase, lane);
    copy_w_async(wsel + 1, Wh, Wl, tid);
    CP_COMMIT(); CP_WAIT0();
    __syncthreads();
    acc_zero(acc);
    mma_stage<8>(Xh, Xl, Wh, Wl, rbase, cbase, lane, acc);
    epi_out(acc, b2, Y, row0, rbase, cbase, lane, relu_out != 0, true);
}

// ---------------- GINE aggregation: h[i] = node[i] + sum relu(node[src]+d*v+c) ---
__device__ __forceinline__ void agg_step(float4& acc, const float4& x, float d,
                                         const float4& v4, const float4& c4)
{
    acc.x += fmaxf(fmaf(d, v4.x, x.x + c4.x), 0.f);
    acc.y += fmaxf(fmaf(d, v4.y, x.y + c4.y), 0.f);
    acc.z += fmaxf(fmaf(d, v4.z, x.z + c4.z), 0.f);
    acc.w += fmaxf(fmaf(d, v4.w, x.w + c4.w), 0.f);
}

__global__ __launch_bounds__(256) void k_agg()
{
    int w = (blockIdx.x * blockDim.x + threadIdx.x) >> 5;
    int lane = threadIdx.x & 31;
    if (w >= NN) return;
    float4 v4 = *(const float4*)(g_v + lane * 4);
    float4 c4 = *(const float4*)(g_c + lane * 4);
    float4 acc = *(const float4*)(g_node + (size_t)w * 128 + lane * 4);
    int e = g_rowptr[w], end = g_rowptr[w + 1];
    for (; e + 8 <= end; e += 8) {
        int2 p[8];
        float4 x[8];
#pragma unroll
        for (int j = 0; j < 8; j++) p[j] = g_ef[e + j];
#pragma unroll
        for (int j = 0; j < 8; j++)
            x[j] = *(const float4*)(g_node + (size_t)p[j].x * 128 + lane * 4);
#pragma unroll
        for (int j = 0; j < 8; j++)
            agg_step(acc, x[j], __int_as_float(p[j].y), v4, c4);
    }
    for (; e < end; e++) {
        int2 p = g_ef[e];
        float4 x = *(const float4*)(g_node + (size_t)p.x * 128 + lane * 4);
        agg_step(acc, x, __int_as_float(p.y), v4, c4);
    }
    *(float4*)(g_h + (size_t)w * 128 + lane * 4) = acc;
}

// ---------------- launch ---------------------------------------------------------
extern "C" void kernel_launch(void* const* d_in, const int* in_sizes, int n_in,
                              void* d_out, int out_size)
{
    const float* z   = (const float*)d_in[0];
    const float* t   = (const float*)d_in[1];
    const float* at  = (const float*)d_in[2];
    const float* ed  = (const float*)d_in[3];
    const int*   ei  = (const int*)d_in[4];
    const int*   na  = (const int*)d_in[5];
    const float* nw1 = (const float*)d_in[6];
    const float* nb1 = (const float*)d_in[7];
    const float* nw2 = (const float*)d_in[8];
    const float* nb2 = (const float*)d_in[9];
    const float* tw1 = (const float*)d_in[10];
    const float* tb1 = (const float*)d_in[11];
    const float* tw2 = (const float*)d_in[12];
    const float* tb2 = (const float*)d_in[13];
    const float* ew1 = (const float*)d_in[14];
    const float* eb1 = (const float*)d_in[15];
    const float* ew2 = (const float*)d_in[16];
    const float* eb2 = (const float*)d_in[17];
    const float* fw1 = (const float*)d_in[18];
    const float* fb1 = (const float*)d_in[19];
    const float* fw2 = (const float*)d_in[20];
    const float* fb2 = (const float*)d_in[21];
    const float* cw1 = (const float*)d_in[22];
    const float* cb1 = (const float*)d_in[23];
    const float* cw2 = (const float*)d_in[24];
    const float* cb2 = (const float*)d_in[25];
    float* out = (float*)d_out;

    cudaFuncSetAttribute(k_atom_t, cudaFuncAttributeMaxDynamicSharedMemorySize, SMEM_MMA);
    cudaFuncSetAttribute(k_node_t, cudaFuncAttributeMaxDynamicSharedMemorySize, SMEM_MMA);
    cudaFuncSetAttribute(k_conv_t, cudaFuncAttributeMaxDynamicSharedMemorySize, SMEM_MMA);

    k_setup<<<(NN + 511) / 512, 512>>>(ew1, eb1, ew2, eb2, na);
    k_mega<<<MEGA_GRID, 512>>>(t, tw1, tb1, tw2, tb2, fw1, fb1, ei,
                               nw1, nw2, fw1, fw1 + 256 * 128, fw2,
                               cw1, cw2, cw1 + 16384, cw2 + 16384,
                               cw1 + 2 * 16384, cw2 + 2 * 16384);
    k_scan<<<1, 1024>>>();
    k_fill<<<(EE + 511) / 512, 512>>>(ei, ed);
    k_atom_t<<<NTILES, 512, SMEM_MMA>>>(at, nb1, nb2);
    k_node_t<<<NTILES, 512, SMEM_MMA>>>(z, fb2);

    for (int i = 0; i < 3; i++) {
        k_agg<<<(NN * 32 + 255) / 256, 256>>>();
        float* Yext = (i == 2) ? out : nullptr;
        k_conv_t<<<NTILES, 512, SMEM_MMA>>>(5 + i * 2, cb1 + i * 128, cb2 + i * 128,
                                            Yext, (i < 2) ? 1 : 0);
    }
}

// round 11
// speedup vs baseline: 1.5214x; 1.1560x over previous
#include <cuda_runtime.h>
#include <cuda_bf16.h>
#include <cuda_fp16.h>
#include <math.h>
#include <stdint.h>

#define NN 20000
#define EE 640000
#define GG 100
#define HH 128
#define TM 64                                  // M tile rows
#define NT64 ((NN + TM - 1) / TM)              // 313
#define P 136                                  // pitch in bf16 (272B rows)
#define WROWS (128 * P)                        // weight tile elements
#define XROWS (64 * P)                         // X tile elements
#define SMEM_MMA ((2 * XROWS + 2 * WROWS) * 2) // Xh|Xl|Wh|Wl = 104448 B

// ---------------- scratch (device globals; no allocation allowed) ----------------
__device__ float  g_node[NN * HH];
__device__ __half g_nf16[NN * HH];             // fp16 shadow of node (gather source)
__device__ float  g_h[NN * HH];
__device__ float  g_ae[NN * HH];
__device__ float  g_TB[GG * HH];
__device__ float  g_v[HH];
__device__ float  g_c[HH];
__device__ int    g_offs[GG + 1];
__device__ int    g_gid[NN];
__device__ int    g_cnt[NN];
__device__ int    g_rowptr[NN + 1];
__device__ int    g_cursor[NN];
__device__ int2   g_ef[EE];
// pre-split weights: [matrix][hi/lo][n*P+k], transposed [n][k]
__device__ __align__(16) __nv_bfloat16 g_wsp[11][2][WROWS];

// ---------------- helpers ---------------------------------------------------------
__device__ __forceinline__ uint32_t smem_u32(const void* p) {
    uint32_t a;
    asm("{ .reg .u64 t; cvta.to.shared.u64 t, %1; cvt.u32.u64 %0, t; }" : "=r"(a) : "l"(p));
    return a;
}
__device__ __forceinline__ void ldsm4(uint32_t r[4], uint32_t addr) {
    asm volatile("ldmatrix.sync.aligned.m8n8.x4.shared.b16 {%0,%1,%2,%3},[%4];"
                 : "=r"(r[0]), "=r"(r[1]), "=r"(r[2]), "=r"(r[3]) : "r"(addr));
}
__device__ __forceinline__ void mma16816(float c[4], const uint32_t a[4], const uint32_t b[2]) {
    asm volatile("mma.sync.aligned.m16n8k16.row.col.f32.bf16.bf16.f32 "
                 "{%0,%1,%2,%3},{%4,%5,%6,%7},{%8,%9},{%0,%1,%2,%3};"
                 : "+f"(c[0]), "+f"(c[1]), "+f"(c[2]), "+f"(c[3])
                 : "r"(a[0]), "r"(a[1]), "r"(a[2]), "r"(a[3]), "r"(b[0]), "r"(b[1]));
}
__device__ __forceinline__ void split_bf(float x, __nv_bfloat16& h, __nv_bfloat16& l) {
    h = __float2bfloat16(x);
    l = __float2bfloat16(x - __bfloat162float(h));
}
__device__ __forceinline__ void cpa16(uint32_t dst, const void* src) {
    asm volatile("cp.async.cg.shared.global [%0],[%1],16;" :: "r"(dst), "l"(src));
}
#define CP_COMMIT() asm volatile("cp.async.commit_group;" ::: "memory")
#define CP_WAIT0()  asm volatile("cp.async.wait_group 0;" ::: "memory")

// ---------------- software-pipelined fused 3-product MMA stage --------------------
template <int KS>
__device__ __forceinline__ void mma_stage(const __nv_bfloat16* __restrict__ Xh,
                                          const __nv_bfloat16* __restrict__ Xl,
                                          const __nv_bfloat16* __restrict__ Wh,
                                          const __nv_bfloat16* __restrict__ Wl,
                                          int rbase, int cbase, int lane,
                                          float acc[2][4][4])
{
    int arow = rbase + (lane & 15);
    int acol = (lane >> 4) << 3;
    int brow = cbase + (lane & 7) + ((lane >> 4) << 3);
    int bcol = ((lane >> 3) & 1) << 3;
    uint32_t ah[2][2][4], al[2][2][4], bh[2][2][4], bl[2][2][4];

#pragma unroll
    for (int mf = 0; mf < 2; mf++) {
        ldsm4(ah[0][mf], smem_u32(Xh + (arow + mf * 16) * P + acol));
        ldsm4(al[0][mf], smem_u32(Xl + (arow + mf * 16) * P + acol));
        ldsm4(bh[0][mf], smem_u32(Wh + (brow + mf * 16) * P + bcol));
        ldsm4(bl[0][mf], smem_u32(Wl + (brow + mf * 16) * P + bcol));
    }
#pragma unroll
    for (int ks = 0; ks < KS; ks++) {
        const int cur = ks & 1, nxt = cur ^ 1;
        if (ks + 1 < KS) {
            int k0 = (ks + 1) * 16;
#pragma unroll
            for (int mf = 0; mf < 2; mf++) {
                ldsm4(ah[nxt][mf], smem_u32(Xh + (arow + mf * 16) * P + k0 + acol));
                ldsm4(al[nxt][mf], smem_u32(Xl + (arow + mf * 16) * P + k0 + acol));
                ldsm4(bh[nxt][mf], smem_u32(Wh + (brow + mf * 16) * P + k0 + bcol));
                ldsm4(bl[nxt][mf], smem_u32(Wl + (brow + mf * 16) * P + k0 + bcol));
            }
        }
#pragma unroll
        for (int mf = 0; mf < 2; mf++)
#pragma unroll
            for (int nf = 0; nf < 4; nf++) {
                const uint32_t* ph = &bh[cur][nf >> 1][(nf & 1) * 2];
                const uint32_t* pl = &bl[cur][nf >> 1][(nf & 1) * 2];
                mma16816(acc[mf][nf], ah[cur][mf], ph);
                mma16816(acc[mf][nf], ah[cur][mf], pl);
                mma16816(acc[mf][nf], al[cur][mf], ph);
            }
    }
}

__device__ __forceinline__ void acc_zero(float acc[2][4][4])
{
#pragma unroll
    for (int mf = 0; mf < 2; mf++)
#pragma unroll
        for (int nf = 0; nf < 4; nf++)
#pragma unroll
            for (int j = 0; j < 4; j++) acc[mf][nf][j] = 0.f;
}

__device__ __forceinline__ void copy_w_async(int m, __nv_bfloat16* Wh, __nv_bfloat16* Wl, int tid)
{
    uint32_t dh = smem_u32(Wh), dl = smem_u32(Wl);
    const char* sh = (const char*)g_wsp[m][0];
    const char* sl = (const char*)g_wsp[m][1];
    for (int i = tid; i < (WROWS * 2) / 16; i += 256) {
        cpa16(dh + i * 16, sh + i * 16);
        cpa16(dl + i * 16, sl + i * 16);
    }
}

// vectorized X split, stride 128, 64 rows
__device__ __forceinline__ void load_x128v(const float* __restrict__ X, int row0,
                                           __nv_bfloat16* Xh, __nv_bfloat16* Xl, int tid)
{
    for (int i = tid; i < 64 * 32; i += 256) {
        int r = i >> 5, q = i & 31;
        int row = row0 + r;
        float4 v = (row < NN) ? *(const float4*)(X + (size_t)row * 128 + q * 4)
                              : make_float4(0.f, 0.f, 0.f, 0.f);
        __nv_bfloat16 h0, l0, h1, l1, h2, l2, h3, l3;
        split_bf(v.x, h0, l0); split_bf(v.y, h1, l1);
        split_bf(v.z, h2, l2); split_bf(v.w, h3, l3);
        int o = r * P + q * 4;
        *(__nv_bfloat162*)(Xh + o)     = __nv_bfloat162{h0, h1};
        *(__nv_bfloat162*)(Xh + o + 2) = __nv_bfloat162{h2, h3};
        *(__nv_bfloat162*)(Xl + o)     = __nv_bfloat162{l0, l1};
        *(__nv_bfloat162*)(Xl + o + 2) = __nv_bfloat162{l2, l3};
    }
}

// vectorized X split, stride 100 padded to 112, 64 rows (atom_types)
__device__ __forceinline__ void load_xatomv(const float* __restrict__ X, int row0,
                                            __nv_bfloat16* Xh, __nv_bfloat16* Xl, int tid)
{
    for (int i = tid; i < 64 * 28; i += 256) {
        int r = i / 28, q = i - r * 28;
        int row = row0 + r;
        float4 v = (q < 25 && row < NN) ? *(const float4*)(X + (size_t)row * 100 + q * 4)
                                        : make_float4(0.f, 0.f, 0.f, 0.f);
        __nv_bfloat16 h0, l0, h1, l1, h2, l2, h3, l3;
        split_bf(v.x, h0, l0); split_bf(v.y, h1, l1);
        split_bf(v.z, h2, l2); split_bf(v.w, h3, l3);
        int o = r * P + q * 4;
        *(__nv_bfloat162*)(Xh + o)     = __nv_bfloat162{h0, h1};
        *(__nv_bfloat162*)(Xh + o + 2) = __nv_bfloat162{h2, h3};
        *(__nv_bfloat162*)(Xl + o)     = __nv_bfloat162{l0, l1};
        *(__nv_bfloat162*)(Xl + o + 2) = __nv_bfloat162{l2, l3};
    }
}

// stage-1 epilogue: acc + bias (or per-row TB) -> relu -> split -> smem X tiles
__device__ __forceinline__ void epi_mid(float acc[2][4][4], const float* __restrict__ bias,
                                        bool use_tb, int row0,
                                        __nv_bfloat16* Xh, __nv_bfloat16* Xl,
                                        int rbase, int cbase, int lane)
{
    int gid = lane >> 2, tig = lane & 3;
#pragma unroll
    for (int mf = 0; mf < 2; mf++) {
#pragma unroll
        for (int half = 0; half < 2; half++) {
            int rl = rbase + mf * 16 + gid + half * 8;
            const float* add;
            if (use_tb) {
                int row = row0 + rl;
                if (row >= NN) row = NN - 1;
                add = &g_TB[(size_t)g_gid[row] * 128];
            } else {
                add = bias;
            }
#pragma unroll
            for (int nf = 0; nf < 4; nf++) {
                int col = cbase + nf * 8 + tig * 2;
                float v0 = fmaxf(acc[mf][nf][half * 2 + 0] + add[col], 0.f);
                float v1 = fmaxf(acc[mf][nf][half * 2 + 1] + add[col + 1], 0.f);
                __nv_bfloat16 h0, l0, h1, l1;
                split_bf(v0, h0, l0);
                split_bf(v1, h1, l1);
                *(__nv_bfloat162*)(Xh + rl * P + col) = __nv_bfloat162{h0, h1};
                *(__nv_bfloat162*)(Xl + rl * P + col) = __nv_bfloat162{l0, l1};
            }
        }
    }
}

// stage-2 epilogue: + bias, [relu], [+g_node residual], fp32 store [+ f16 shadow]
__device__ __forceinline__ void epi_out(float acc[2][4][4], const float* __restrict__ bias,
                                        float* __restrict__ Y, __half* __restrict__ Yf16,
                                        int row0, int rbase, int cbase, int lane,
                                        bool relu, bool resid)
{
    int gid = lane >> 2, tig = lane & 3;
#pragma unroll
    for (int mf = 0; mf < 2; mf++) {
#pragma unroll
        for (int half = 0; half < 2; half++) {
            int row = row0 + rbase + mf * 16 + gid + half * 8;
            if (row >= NN) continue;
#pragma unroll
            for (int nf = 0; nf < 4; nf++) {
                int col = cbase + nf * 8 + tig * 2;
                float v0 = acc[mf][nf][half * 2 + 0] + bias[col];
                float v1 = acc[mf][nf][half * 2 + 1] + bias[col + 1];
                if (relu) { v0 = fmaxf(v0, 0.f); v1 = fmaxf(v1, 0.f); }
                if (resid) {
                    float2 nd = *(const float2*)(g_node + (size_t)row * 128 + col);
                    v0 += nd.x; v1 += nd.y;
                }
                *(float2*)(Y + (size_t)row * 128 + col) = make_float2(v0, v1);
                if (Yf16)
                    *(__half2*)(Yf16 + (size_t)row * 128 + col) =
                        __floats2half2_rn(v0, v1);
            }
        }
    }
}

// ---------------- setup: offsets + rank-1 edge vector + zero counters -------------
__global__ __launch_bounds__(512) void k_setup(const float* __restrict__ ew1, const float* __restrict__ eb1,
                                               const float* __restrict__ ew2, const float* __restrict__ eb2,
                                               const int* __restrict__ num_atoms)
{
    int b = blockIdx.x, t = threadIdx.x;
    int i = b * 512 + t;
    if (i < NN) g_cnt[i] = 0;
    if (b != 0) return;
    __shared__ int s_na[GG];
    __shared__ int s_off[GG + 1];
    if (t < GG) s_na[t] = num_atoms[t];
    __syncthreads();
    if (t == 0) {
        int o = 0;
        for (int g = 0; g < GG; g++) { s_off[g] = o; o += s_na[g]; }
        s_off[GG] = o;
    }
    __syncthreads();
    if (t <= GG) g_offs[t] = s_off[t];
    if (t < HH) {
        float v = 0.f, c = 0.f;
        for (int j = 0; j < HH; j++) {
            float w = ew1[j];
            if (w > 0.f) {
                float w2 = ew2[j * HH + t];
                v = fmaf(w, w2, v);
                c = fmaf(eb1[j], w2, c);
            }
        }
        g_v[t] = v;
        g_c[t] = c + eb2[t];
    }
}

// ---------------- mega prologue: weights + temb + gid + edge count ----------------
#define MB_W    44
#define MB_T    (MB_W + GG)              // 144
#define MB_G    (MB_T + 40)              // 184
#define MB_C    (MB_G + 200)             // 384
#define MEGA_GRID MB_C

__global__ __launch_bounds__(512) void k_mega(
    const float* __restrict__ t_in,
    const float* __restrict__ tw1, const float* __restrict__ tb1,
    const float* __restrict__ tw2, const float* __restrict__ tb2,
    const float* __restrict__ fw1, const float* __restrict__ fb1,
    const int* __restrict__ ei,
    const float* __restrict__ w0, const float* __restrict__ w1,
    const float* __restrict__ w2, const float* __restrict__ w3,
    const float* __restrict__ w4, const float* __restrict__ w5,
    const float* __restrict__ w6, const float* __restrict__ w7,
    const float* __restrict__ w8, const float* __restrict__ w9,
    const float* __restrict__ w10)
{
    __shared__ float emb[128];
    __shared__ float mid[512];
    __shared__ float part[512];
    __shared__ float tout[128];
    int b = blockIdx.x, tid = threadIdx.x;

    if (b < MB_W) {
        int m = b >> 2, quarter = b & 3;
        const float* W;
        switch (m) {
            case 0: W = w0; break;  case 1: W = w1; break;  case 2: W = w2; break;
            case 3: W = w3; break;  case 4: W = w4; break;  case 5: W = w5; break;
            case 6: W = w6; break;  case 7: W = w7; break;  case 8: W = w8; break;
            case 9: W = w9; break;  default: W = w10; break;
        }
        int kreal = (m == 0) ? 100 : 128;
        for (int j = quarter * 4096 + tid; j < (quarter + 1) * 4096; j += 512) {
            int n = j >> 7, k = j & 127;
            float x = (k < kreal) ? W[k * 128 + n] : 0.f;
            __nv_bfloat16 h, l;
            split_bf(x, h, l);
            g_wsp[m][0][n * P + k] = h;
            g_wsp[m][1][n * P + k] = l;
        }
    } else if (b < MB_T) {
        int g = b - MB_W;
        if (tid < 128) {
            float tv = t_in[g];
            int i = tid & 63;
            float freq = expf(-9.2103403719761836f * (float)i / 63.0f);
            float a = tv * freq;
            emb[tid] = (tid < 64) ? sinf(a) : cosf(a);
        }
        __syncthreads();
        {
            int col = tid;
            float a0 = 0.f, a1 = 0.f, a2 = 0.f, a3 = 0.f;
#pragma unroll 8
            for (int j = 0; j < 128; j += 4) {
                a0 = fmaf(emb[j + 0], tw1[(j + 0) * 512 + col], a0);
                a1 = fmaf(emb[j + 1], tw1[(j + 1) * 512 + col], a1);
                a2 = fmaf(emb[j + 2], tw1[(j + 2) * 512 + col], a2);
                a3 = fmaf(emb[j + 3], tw1[(j + 3) * 512 + col], a3);
            }
            mid[col] = fmaxf((a0 + a1) + (a2 + a3) + tb1[col], 0.f);
        }
        __syncthreads();
        {
            int col = tid & 127, chunk = tid >> 7;
            const float* m0 = mid + chunk * 128;
            const float* wp = tw2 + chunk * 128 * 128;
            float a0 = 0.f, a1 = 0.f, a2 = 0.f, a3 = 0.f;
#pragma unroll 8
            for (int j = 0; j < 128; j += 4) {
                a0 = fmaf(m0[j + 0], wp[(j + 0) * 128 + col], a0);
                a1 = fmaf(m0[j + 1], wp[(j + 1) * 128 + col], a1);
                a2 = fmaf(m0[j + 2], wp[(j + 2) * 128 + col], a2);
                a3 = fmaf(m0[j + 3], wp[(j + 3) * 128 + col], a3);
            }
            part[tid] = (a0 + a1) + (a2 + a3);
        }
        __syncthreads();
        if (tid < 128)
            tout[tid] = part[tid] + part[tid + 128] + part[tid + 256] + part[tid + 384] + tb2[tid];
        __syncthreads();
        if (tid < 128) {
            int col = tid;
            float a0 = 0.f, a1 = 0.f, a2 = 0.f, a3 = 0.f;
#pragma unroll 8
            for (int j = 0; j < 128; j += 4) {
                a0 = fmaf(tout[j + 0], fw1[(128 + j + 0) * 128 + col], a0);
                a1 = fmaf(tout[j + 1], fw1[(128 + j + 1) * 128 + col], a1);
                a2 = fmaf(tout[j + 2], fw1[(128 + j + 2) * 128 + col], a2);
                a3 = fmaf(tout[j + 3], fw1[(128 + j + 3) * 128 + col], a3);
            }
            g_TB[g * 128 + col] = (a0 + a1) + (a2 + a3) + fb1[col];
        }
    } else if (b < MB_G) {
        int i = (b - MB_T) * 512 + tid;
        if (i < NN) {
            int lo = 0, hi = GG;
            while (hi - lo > 1) {
                int m = (lo + hi) >> 1;
                if (g_offs[m] <= i) lo = m; else hi = m;
            }
            g_gid[i] = lo;
        }
    } else {
        int base = (b - MB_G) * 3200;
        for (int j = tid; j < 3200; j += 512) {
            int e = base + j;
            if (e < EE) atomicAdd(&g_cnt[ei[EE + e]], 1);
        }
    }
}

// ---------------- CSR build ------------------------------------------------------
__global__ void k_scan()
{
    const int CH = 20;
    __shared__ int ssum[1024];
    int t = threadIdx.x;
    int base = t * CH;
    int s = 0;
    for (int k = 0; k < CH; k++) {
        int idx = base + k;
        if (idx < NN) s += g_cnt[idx];
    }
    ssum[t] = s;
    __syncthreads();
    for (int off = 1; off < 1024; off <<= 1) {
        int v = (t >= off) ? ssum[t - off] : 0;
        __syncthreads();
        ssum[t] += v;
        __syncthreads();
    }
    int run = (t > 0) ? ssum[t - 1] : 0;
    for (int k = 0; k < CH; k++) {
        int idx = base + k;
        if (idx < NN) {
            g_rowptr[idx] = run;
            g_cursor[idx] = run;
            run += g_cnt[idx];
        }
    }
    if (t == 0) g_rowptr[NN] = EE;
}

__global__ void k_fill(const int* __restrict__ ei, const float* __restrict__ ed)
{
    int e = blockIdx.x * blockDim.x + threadIdx.x;
    if (e >= EE) return;
    int dst = ei[EE + e];
    int pos = atomicAdd(&g_cursor[dst], 1);
    g_ef[pos] = make_int2(ei[e], __float_as_int(ed[e]));
}

// ---------------- atom_emb = MLP2(atom_types) : 100 -> 128 -> 128 ----------------
__global__ __launch_bounds__(256, 2) void k_atom_t(const float* __restrict__ X,
                                                   const float* __restrict__ b1,
                                                   const float* __restrict__ b2)
{
    extern __shared__ __nv_bfloat16 sm[];
    __nv_bfloat16 *Xh = sm, *Xl = sm + XROWS;
    __nv_bfloat16 *Wh = sm + 2 * XROWS, *Wl = sm + 2 * XROWS + WROWS;
    int tid = threadIdx.x, wid = tid >> 5, lane = tid & 31;
    int rbase = (wid & 1) * 32, cbase = (wid >> 1) * 32;
    int row0 = blockIdx.x * TM;
    float acc[2][4][4];

    copy_w_async(0, Wh, Wl, tid);
    CP_COMMIT();
    load_xatomv(X, row0, Xh, Xl, tid);
    CP_WAIT0();
    __syncthreads();
    acc_zero(acc);
    mma_stage<7>(Xh, Xl, Wh, Wl, rbase, cbase, lane, acc);
    __syncthreads();
    epi_mid(acc, b1, false, row0, Xh, Xl, rbase, cbase, lane);
    copy_w_async(1, Wh, Wl, tid);
    CP_COMMIT(); CP_WAIT0();
    __syncthreads();
    acc_zero(acc);
    mma_stage<8>(Xh, Xl, Wh, Wl, rbase, cbase, lane, acc);
    epi_out(acc, b2, g_ae, nullptr, row0, rbase, cbase, lane, false, false);
}

// ---------------- node = relu(z@A + ae@C + TB[g]) @ fw2 + fb2 --------------------
__global__ __launch_bounds__(256, 2) void k_node_t(const float* __restrict__ Z,
                                                   const float* __restrict__ fb2)
{
    extern __shared__ __nv_bfloat16 sm[];
    __nv_bfloat16 *Xh = sm, *Xl = sm + XROWS;
    __nv_bfloat16 *Wh = sm + 2 * XROWS, *Wl = sm + 2 * XROWS + WROWS;
    int tid = threadIdx.x, wid = tid >> 5, lane = tid & 31;
    int rbase = (wid & 1) * 32, cbase = (wid >> 1) * 32;
    int row0 = blockIdx.x * TM;
    float acc[2][4][4];

    copy_w_async(2, Wh, Wl, tid);
    CP_COMMIT();
    load_x128v(Z, row0, Xh, Xl, tid);
    CP_WAIT0();
    __syncthreads();
    acc_zero(acc);
    mma_stage<8>(Xh, Xl, Wh, Wl, rbase, cbase, lane, acc);
    __syncthreads();
    copy_w_async(3, Wh, Wl, tid);
    CP_COMMIT();
    load_x128v(g_ae, row0, Xh, Xl, tid);
    CP_WAIT0();
    __syncthreads();
    mma_stage<8>(Xh, Xl, Wh, Wl, rbase, cbase, lane, acc);
    __syncthreads();
    epi_mid(acc, nullptr, true, row0, Xh, Xl, rbase, cbase, lane);
    copy_w_async(4, Wh, Wl, tid);
    CP_COMMIT(); CP_WAIT0();
    __syncthreads();
    acc_zero(acc);
    mma_stage<8>(Xh, Xl, Wh, Wl, rbase, cbase, lane, acc);
    epi_out(acc, fb2, g_node, g_nf16, row0, rbase, cbase, lane, false, false);
}

// ---------------- conv MLP: Y = [relu](relu(h@W1+b1)@W2+b2) + node ---------------
__global__ __launch_bounds__(256, 2) void k_conv_t(int wsel,
                                                   const float* __restrict__ b1,
                                                   const float* __restrict__ b2,
                                                   float* __restrict__ Yext, int relu_out)
{
    extern __shared__ __nv_bfloat16 sm[];
    __nv_bfloat16 *Xh = sm, *Xl = sm + XROWS;
    __nv_bfloat16 *Wh = sm + 2 * XROWS, *Wl = sm + 2 * XROWS + WROWS;
    int tid = threadIdx.x, wid = tid >> 5, lane = tid & 31;
    int rbase = (wid & 1) * 32, cbase = (wid >> 1) * 32;
    int row0 = blockIdx.x * TM;
    float* Y = Yext ? Yext : g_node;
    __half* Yf16 = Yext ? nullptr : g_nf16;
    float acc[2][4][4];

    copy_w_async(wsel, Wh, Wl, tid);
    CP_COMMIT();
    load_x128v(g_h, row0, Xh, Xl, tid);
    CP_WAIT0();
    __syncthreads();
    acc_zero(acc);
    mma_stage<8>(Xh, Xl, Wh, Wl, rbase, cbase, lane, acc);
    __syncthreads();
    epi_mid(acc, b1, false, row0, Xh, Xl, rbase, cbase, lane);
    copy_w_async(wsel + 1, Wh, Wl, tid);
    CP_COMMIT(); CP_WAIT0();
    __syncthreads();
    acc_zero(acc);
    mma_stage<8>(Xh, Xl, Wh, Wl, rbase, cbase, lane, acc);
    epi_out(acc, b2, Y, Yf16, row0, rbase, cbase, lane, relu_out != 0, true);
}

// ---------------- GINE aggregation (fp16 gather) ----------------------------------
__device__ __forceinline__ float4 ldh4(const __half* __restrict__ p)
{
    uint2 u = *(const uint2*)p;
    __half2 h01 = *(__half2*)&u.x;
    __half2 h23 = *(__half2*)&u.y;
    float2 f01 = __half22float2(h01);
    float2 f23 = __half22float2(h23);
    return make_float4(f01.x, f01.y, f23.x, f23.y);
}

__device__ __forceinline__ void agg_step(float4& acc, const float4& x, float d,
                                         const float4& v4, const float4& c4)
{
    acc.x += fmaxf(fmaf(d, v4.x, x.x + c4.x), 0.f);
    acc.y += fmaxf(fmaf(d, v4.y, x.y + c4.y), 0.f);
    acc.z += fmaxf(fmaf(d, v4.z, x.z + c4.z), 0.f);
    acc.w += fmaxf(fmaf(d, v4.w, x.w + c4.w), 0.f);
}

__global__ __launch_bounds__(256) void k_agg()
{
    int w = (blockIdx.x * blockDim.x + threadIdx.x) >> 5;
    int lane = threadIdx.x & 31;
    if (w >= NN) return;
    float4 v4 = *(const float4*)(g_v + lane * 4);
    float4 c4 = *(const float4*)(g_c + lane * 4);
    float4 acc = *(const float4*)(g_node + (size_t)w * 128 + lane * 4);
    int e = g_rowptr[w], end = g_rowptr[w + 1];
    for (; e + 8 <= end; e += 8) {
        int2 p[8];
        float4 x[8];
#pragma unroll
        for (int j = 0; j < 8; j++) p[j] = g_ef[e + j];
#pragma unroll
        for (int j = 0; j < 8; j++)
            x[j] = ldh4(g_nf16 + (size_t)p[j].x * 128 + lane * 4);
#pragma unroll
        for (int j = 0; j < 8; j++)
            agg_step(acc, x[j], __int_as_float(p[j].y), v4, c4);
    }
    for (; e < end; e++) {
        int2 p = g_ef[e];
        float4 x = ldh4(g_nf16 + (size_t)p.x * 128 + lane * 4);
        agg_step(acc, x, __int_as_float(p.y), v4, c4);
    }
    *(float4*)(g_h + (size_t)w * 128 + lane * 4) = acc;
}

// ---------------- launch ---------------------------------------------------------
extern "C" void kernel_launch(void* const* d_in, const int* in_sizes, int n_in,
                              void* d_out, int out_size)
{
    const float* z   = (const float*)d_in[0];
    const float* t   = (const float*)d_in[1];
    const float* at  = (const float*)d_in[2];
    const float* ed  = (const float*)d_in[3];
    const int*   ei  = (const int*)d_in[4];
    const int*   na  = (const int*)d_in[5];
    const float* nw1 = (const float*)d_in[6];
    const float* nb1 = (const float*)d_in[7];
    const float* nw2 = (const float*)d_in[8];
    const float* nb2 = (const float*)d_in[9];
    const float* tw1 = (const float*)d_in[10];
    const float* tb1 = (const float*)d_in[11];
    const float* tw2 = (const float*)d_in[12];
    const float* tb2 = (const float*)d_in[13];
    const float* ew1 = (const float*)d_in[14];
    const float* eb1 = (const float*)d_in[15];
    const float* ew2 = (const float*)d_in[16];
    const float* eb2 = (const float*)d_in[17];
    const float* fw1 = (const float*)d_in[18];
    const float* fb1 = (const float*)d_in[19];
    const float* fw2 = (const float*)d_in[20];
    const float* fb2 = (const float*)d_in[21];
    const float* cw1 = (const float*)d_in[22];
    const float* cb1 = (const float*)d_in[23];
    const float* cw2 = (const float*)d_in[24];
    const float* cb2 = (const float*)d_in[25];
    float* out = (float*)d_out;

    cudaFuncSetAttribute(k_atom_t, cudaFuncAttributeMaxDynamicSharedMemorySize, SMEM_MMA);
    cudaFuncSetAttribute(k_node_t, cudaFuncAttributeMaxDynamicSharedMemorySize, SMEM_MMA);
    cudaFuncSetAttribute(k_conv_t, cudaFuncAttributeMaxDynamicSharedMemorySize, SMEM_MMA);

    k_setup<<<(NN + 511) / 512, 512>>>(ew1, eb1, ew2, eb2, na);
    k_mega<<<MEGA_GRID, 512>>>(t, tw1, tb1, tw2, tb2, fw1, fb1, ei,
                               nw1, nw2, fw1, fw1 + 256 * 128, fw2,
                               cw1, cw2, cw1 + 16384, cw2 + 16384,
                               cw1 + 2 * 16384, cw2 + 2 * 16384);
    k_scan<<<1, 1024>>>();
    k_fill<<<(EE + 511) / 512, 512>>>(ei, ed);
    k_atom_t<<<NT64, 256, SMEM_MMA>>>(at, nb1, nb2);
    k_node_t<<<NT64, 256, SMEM_MMA>>>(z, fb2);

    for (int i = 0; i < 3; i++) {
        k_agg<<<(NN * 32 + 255) / 256, 256>>>();
        float* Yext = (i == 2) ? out : nullptr;
        k_conv_t<<<NT64, 256, SMEM_MMA>>>(5 + i * 2, cb1 + i * 128, cb2 + i * 128,
                                          Yext, (i < 2) ? 1 : 0);
    }
}

// round 14
// speedup vs baseline: 1.6769x; 1.1022x over previous
#include <cuda_runtime.h>
#include <cuda_fp16.h>
#include <math.h>
#include <stdint.h>

#define NN 20000
#define EE 640000
#define GG 100
#define HH 128
#define TM 64                                  // M tile rows
#define NT64 ((NN + TM - 1) / TM)              // 313
#define P 136                                  // pitch in fp16 (272B rows)
#define WROWS (128 * P)                        // weight tile elements
#define XROWS (64 * P)                         // X tile elements
#define SMEM_MMA ((XROWS + 2 * WROWS) * 2)     // X|Wh|Wl = 87040 B
#define XS  0.015625f                          // X-tile scale 1/64 (exact pow2)
#define XSI 64.0f                              // inverse scale

// ---------------- scratch (device globals; no allocation allowed) ----------------
__device__ float  g_node[NN * HH];
__device__ __half g_nf16[NN * HH];             // fp16 shadow of node (gather source)
__device__ float  g_h[NN * HH];
__device__ float  g_ae[NN * HH];
__device__ float  g_TB[GG * HH];
__device__ float  g_v[HH];
__device__ float  g_c[HH];
__device__ int    g_offs[GG + 1];
__device__ int    g_gid[NN];
__device__ int    g_cnt[NN];
__device__ int    g_rowptr[NN + 1];
__device__ int    g_cursor[NN];
__device__ int2   g_ef[EE];
// pre-split fp16 weights: [matrix][hi/lo][n*P+k], transposed [n][k]
__device__ __align__(16) __half g_wsp[11][2][WROWS];

// ---------------- helpers ---------------------------------------------------------
__device__ __forceinline__ uint32_t smem_u32(const void* p) {
    uint32_t a;
    asm("{ .reg .u64 t; cvta.to.shared.u64 t, %1; cvt.u32.u64 %0, t; }" : "=r"(a) : "l"(p));
    return a;
}
__device__ __forceinline__ void ldsm4(uint32_t r[4], uint32_t addr) {
    asm volatile("ldmatrix.sync.aligned.m8n8.x4.shared.b16 {%0,%1,%2,%3},[%4];"
                 : "=r"(r[0]), "=r"(r[1]), "=r"(r[2]), "=r"(r[3]) : "r"(addr));
}
__device__ __forceinline__ void mma16816(float c[4], const uint32_t a[4], const uint32_t b[2]) {
    asm volatile("mma.sync.aligned.m16n8k16.row.col.f32.f16.f16.f32 "
                 "{%0,%1,%2,%3},{%4,%5,%6,%7},{%8,%9},{%0,%1,%2,%3};"
                 : "+f"(c[0]), "+f"(c[1]), "+f"(c[2]), "+f"(c[3])
                 : "r"(a[0]), "r"(a[1]), "r"(a[2]), "r"(a[3]), "r"(b[0]), "r"(b[1]));
}
__device__ __forceinline__ void split_h(float x, __half& h, __half& l) {
    h = __float2half(x);
    l = __float2half(x - __half2float(h));
}
__device__ __forceinline__ void cpa16(uint32_t dst, const void* src) {
    asm volatile("cp.async.cg.shared.global [%0],[%1],16;" :: "r"(dst), "l"(src));
}
#define CP_COMMIT() asm volatile("cp.async.commit_group;" ::: "memory")
#define CP_WAIT0()  asm volatile("cp.async.wait_group 0;" ::: "memory")

// ---------------- software-pipelined 2-product MMA stage (fp16 X/64, split-fp16 W) -
template <int KS>
__device__ __forceinline__ void mma_stage(const __half* __restrict__ X,
                                          const __half* __restrict__ Wh,
                                          const __half* __restrict__ Wl,
                                          int rbase, int cbase, int lane,
                                          float acc[2][4][4])
{
    int arow = rbase + (lane & 15);
    int acol = (lane >> 4) << 3;
    int brow = cbase + (lane & 7) + ((lane >> 4) << 3);
    int bcol = ((lane >> 3) & 1) << 3;
    uint32_t a[2][2][4], bh[2][2][4], bl[2][2][4];   // [buf][frag][4]

#pragma unroll
    for (int mf = 0; mf < 2; mf++) {
        ldsm4(a[0][mf],  smem_u32(X  + (arow + mf * 16) * P + acol));
        ldsm4(bh[0][mf], smem_u32(Wh + (brow + mf * 16) * P + bcol));
        ldsm4(bl[0][mf], smem_u32(Wl + (brow + mf * 16) * P + bcol));
    }
#pragma unroll
    for (int ks = 0; ks < KS; ks++) {
        const int cur = ks & 1, nxt = cur ^ 1;
        if (ks + 1 < KS) {
            int k0 = (ks + 1) * 16;
#pragma unroll
            for (int mf = 0; mf < 2; mf++) {
                ldsm4(a[nxt][mf],  smem_u32(X  + (arow + mf * 16) * P + k0 + acol));
                ldsm4(bh[nxt][mf], smem_u32(Wh + (brow + mf * 16) * P + k0 + bcol));
                ldsm4(bl[nxt][mf], smem_u32(Wl + (brow + mf * 16) * P + k0 + bcol));
            }
        }
#pragma unroll
        for (int mf = 0; mf < 2; mf++)
#pragma unroll
            for (int nf = 0; nf < 4; nf++) {
                const uint32_t* ph = &bh[cur][nf >> 1][(nf & 1) * 2];
                const uint32_t* pl = &bl[cur][nf >> 1][(nf & 1) * 2];
                mma16816(acc[mf][nf], a[cur][mf], ph);
                mma16816(acc[mf][nf], a[cur][mf], pl);
            }
    }
}

__device__ __forceinline__ void acc_zero(float acc[2][4][4])
{
#pragma unroll
    for (int mf = 0; mf < 2; mf++)
#pragma unroll
        for (int nf = 0; nf < 4; nf++)
#pragma unroll
            for (int j = 0; j < 4; j++) acc[mf][nf][j] = 0.f;
}

__device__ __forceinline__ void copy_w_async(int m, __half* Wh, __half* Wl, int tid)
{
    uint32_t dh = smem_u32(Wh), dl = smem_u32(Wl);
    const char* sh = (const char*)g_wsp[m][0];
    const char* sl = (const char*)g_wsp[m][1];
    for (int i = tid; i < (WROWS * 2) / 16; i += 256) {
        cpa16(dh + i * 16, sh + i * 16);
        cpa16(dl + i * 16, sl + i * 16);
    }
}

// vectorized X load -> fp16/64 tile, stride 128, 64 rows
__device__ __forceinline__ void load_x128v(const float* __restrict__ X, int row0,
                                           __half* Xs, int tid)
{
    for (int i = tid; i < 64 * 32; i += 256) {
        int r = i >> 5, q = i & 31;
        int row = row0 + r;
        float4 v = (row < NN) ? *(const float4*)(X + (size_t)row * 128 + q * 4)
                              : make_float4(0.f, 0.f, 0.f, 0.f);
        int o = r * P + q * 4;
        *(__half2*)(Xs + o)     = __floats2half2_rn(v.x * XS, v.y * XS);
        *(__half2*)(Xs + o + 2) = __floats2half2_rn(v.z * XS, v.w * XS);
    }
}

// vectorized X load -> fp16/64, stride 100 padded to 112, 64 rows (atom_types)
__device__ __forceinline__ void load_xatomv(const float* __restrict__ X, int row0,
                                            __half* Xs, int tid)
{
    for (int i = tid; i < 64 * 28; i += 256) {
        int r = i / 28, q = i - r * 28;
        int row = row0 + r;
        float4 v = (q < 25 && row < NN) ? *(const float4*)(X + (size_t)row * 100 + q * 4)
                                        : make_float4(0.f, 0.f, 0.f, 0.f);
        int o = r * P + q * 4;
        *(__half2*)(Xs + o)     = __floats2half2_rn(v.x * XS, v.y * XS);
        *(__half2*)(Xs + o + 2) = __floats2half2_rn(v.z * XS, v.w * XS);
    }
}

// stage-1 epilogue: acc*64 + bias (or per-row TB) -> relu -> fp16/64 -> smem X tile
__device__ __forceinline__ void epi_mid(float acc[2][4][4], const float* __restrict__ bias,
                                        bool use_tb, int row0, __half* Xs,
                                        int rbase, int cbase, int lane)
{
    int gid = lane >> 2, tig = lane & 3;
#pragma unroll
    for (int mf = 0; mf < 2; mf++) {
#pragma unroll
        for (int half = 0; half < 2; half++) {
            int rl = rbase + mf * 16 + gid + half * 8;
            const float* add;
            if (use_tb) {
                int row = row0 + rl;
                if (row >= NN) row = NN - 1;
                add = &g_TB[(size_t)g_gid[row] * 128];
            } else {
                add = bias;
            }
#pragma unroll
            for (int nf = 0; nf < 4; nf++) {
                int col = cbase + nf * 8 + tig * 2;
                float v0 = fmaxf(fmaf(acc[mf][nf][half * 2 + 0], XSI, add[col]), 0.f);
                float v1 = fmaxf(fmaf(acc[mf][nf][half * 2 + 1], XSI, add[col + 1]), 0.f);
                *(__half2*)(Xs + rl * P + col) = __floats2half2_rn(v0 * XS, v1 * XS);
            }
        }
    }
}

// stage-2 epilogue: acc*64 + bias, [relu], [+g_node residual], fp32 store [+ f16 shadow]
__device__ __forceinline__ void epi_out(float acc[2][4][4], const float* __restrict__ bias,
                                        float* __restrict__ Y, __half* __restrict__ Yf16,
                                        int row0, int rbase, int cbase, int lane,
                                        bool relu, bool resid)
{
    int gid = lane >> 2, tig = lane & 3;
#pragma unroll
    for (int mf = 0; mf < 2; mf++) {
#pragma unroll
        for (int half = 0; half < 2; half++) {
            int row = row0 + rbase + mf * 16 + gid + half * 8;
            if (row >= NN) continue;
#pragma unroll
            for (int nf = 0; nf < 4; nf++) {
                int col = cbase + nf * 8 + tig * 2;
                float v0 = fmaf(acc[mf][nf][half * 2 + 0], XSI, bias[col]);
                float v1 = fmaf(acc[mf][nf][half * 2 + 1], XSI, bias[col + 1]);
                if (relu) { v0 = fmaxf(v0, 0.f); v1 = fmaxf(v1, 0.f); }
                if (resid) {
                    float2 nd = *(const float2*)(g_node + (size_t)row * 128 + col);
                    v0 += nd.x; v1 += nd.y;
                }
                *(float2*)(Y + (size_t)row * 128 + col) = make_float2(v0, v1);
                if (Yf16)
                    *(__half2*)(Yf16 + (size_t)row * 128 + col) =
                        __floats2half2_rn(v0, v1);
            }
        }
    }
}

// ---------------- setup: offsets + rank-1 edge vector + zero counters -------------
__global__ __launch_bounds__(512) void k_setup(const float* __restrict__ ew1, const float* __restrict__ eb1,
                                               const float* __restrict__ ew2, const float* __restrict__ eb2,
                                               const int* __restrict__ num_atoms)
{
    int b = blockIdx.x, t = threadIdx.x;
    int i = b * 512 + t;
    if (i < NN) g_cnt[i] = 0;
    if (b != 0) return;
    __shared__ int s_na[GG];
    __shared__ int s_off[GG + 1];
    if (t < GG) s_na[t] = num_atoms[t];
    __syncthreads();
    if (t == 0) {
        int o = 0;
        for (int g = 0; g < GG; g++) { s_off[g] = o; o += s_na[g]; }
        s_off[GG] = o;
    }
    __syncthreads();
    if (t <= GG) g_offs[t] = s_off[t];
    if (t < HH) {
        float v = 0.f, c = 0.f;
        for (int j = 0; j < HH; j++) {
            float w = ew1[j];
            if (w > 0.f) {
                float w2 = ew2[j * HH + t];
                v = fmaf(w, w2, v);
                c = fmaf(eb1[j], w2, c);
            }
        }
        g_v[t] = v;
        g_c[t] = c + eb2[t];
    }
}

// ---------------- mega prologue: weights + temb + gid + edge count ----------------
#define MB_W    44
#define MB_T    (MB_W + GG)              // 144
#define MB_G    (MB_T + 40)              // 184
#define MB_C    (MB_G + 200)             // 384
#define MEGA_GRID MB_C

__global__ __launch_bounds__(512) void k_mega(
    const float* __restrict__ t_in,
    const float* __restrict__ tw1, const float* __restrict__ tb1,
    const float* __restrict__ tw2, const float* __restrict__ tb2,
    const float* __restrict__ fw1, const float* __restrict__ fb1,
    const int* __restrict__ ei,
    const float* __restrict__ w0, const float* __restrict__ w1,
    const float* __restrict__ w2, const float* __restrict__ w3,
    const float* __restrict__ w4, const float* __restrict__ w5,
    const float* __restrict__ w6, const float* __restrict__ w7,
    const float* __restrict__ w8, const float* __restrict__ w9,
    const float* __restrict__ w10)
{
    __shared__ float emb[128];
    __shared__ float mid[512];
    __shared__ float part[512];
    __shared__ float tout[128];
    int b = blockIdx.x, tid = threadIdx.x;

    if (b < MB_W) {
        int m = b >> 2, quarter = b & 3;
        const float* W;
        switch (m) {
            case 0: W = w0; break;  case 1: W = w1; break;  case 2: W = w2; break;
            case 3: W = w3; break;  case 4: W = w4; break;  case 5: W = w5; break;
            case 6: W = w6; break;  case 7: W = w7; break;  case 8: W = w8; break;
            case 9: W = w9; break;  default: W = w10; break;
        }
        int kreal = (m == 0) ? 100 : 128;
        for (int j = quarter * 4096 + tid; j < (quarter + 1) * 4096; j += 512) {
            int n = j >> 7, k = j & 127;
            float x = (k < kreal) ? W[k * 128 + n] : 0.f;
            __half h, l;
            split_h(x, h, l);
            g_wsp[m][0][n * P + k] = h;
            g_wsp[m][1][n * P + k] = l;
        }
    } else if (b < MB_T) {
        int g = b - MB_W;
        if (tid < 128) {
            float tv = t_in[g];
            int i = tid & 63;
            float freq = expf(-9.2103403719761836f * (float)i / 63.0f);
            float a = tv * freq;
            emb[tid] = (tid < 64) ? sinf(a) : cosf(a);
        }
        __syncthreads();
        {
            int col = tid;
            float a0 = 0.f, a1 = 0.f, a2 = 0.f, a3 = 0.f;
#pragma unroll 8
            for (int j = 0; j < 128; j += 4) {
                a0 = fmaf(emb[j + 0], tw1[(j + 0) * 512 + col], a0);
                a1 = fmaf(emb[j + 1], tw1[(j + 1) * 512 + col], a1);
                a2 = fmaf(emb[j + 2], tw1[(j + 2) * 512 + col], a2);
                a3 = fmaf(emb[j + 3], tw1[(j + 3) * 512 + col], a3);
            }
            mid[col] = fmaxf((a0 + a1) + (a2 + a3) + tb1[col], 0.f);
        }
        __syncthreads();
        {
            int col = tid & 127, chunk = tid >> 7;
            const float* m0 = mid + chunk * 128;
            const float* wp = tw2 + chunk * 128 * 128;
            float a0 = 0.f, a1 = 0.f, a2 = 0.f, a3 = 0.f;
#pragma unroll 8
            for (int j = 0; j < 128; j += 4) {
                a0 = fmaf(m0[j + 0], wp[(j + 0) * 128 + col], a0);
                a1 = fmaf(m0[j + 1], wp[(j + 1) * 128 + col], a1);
                a2 = fmaf(m0[j + 2], wp[(j + 2) * 128 + col], a2);
                a3 = fmaf(m0[j + 3], wp[(j + 3) * 128 + col], a3);
            }
            part[tid] = (a0 + a1) + (a2 + a3);
        }
        __syncthreads();
        if (tid < 128)
            tout[tid] = part[tid] + part[tid + 128] + part[tid + 256] + part[tid + 384] + tb2[tid];
        __syncthreads();
        if (tid < 128) {
            int col = tid;
            float a0 = 0.f, a1 = 0.f, a2 = 0.f, a3 = 0.f;
#pragma unroll 8
            for (int j = 0; j < 128; j += 4) {
                a0 = fmaf(tout[j + 0], fw1[(128 + j + 0) * 128 + col], a0);
                a1 = fmaf(tout[j + 1], fw1[(128 + j + 1) * 128 + col], a1);
                a2 = fmaf(tout[j + 2], fw1[(128 + j + 2) * 128 + col], a2);
                a3 = fmaf(tout[j + 3], fw1[(128 + j + 3) * 128 + col], a3);
            }
            g_TB[g * 128 + col] = (a0 + a1) + (a2 + a3) + fb1[col];
        }
    } else if (b < MB_G) {
        int i = (b - MB_T) * 512 + tid;
        if (i < NN) {
            int lo = 0, hi = GG;
            while (hi - lo > 1) {
                int m = (lo + hi) >> 1;
                if (g_offs[m] <= i) lo = m; else hi = m;
            }
            g_gid[i] = lo;
        }
    } else {
        int base = (b - MB_G) * 3200;
        for (int j = tid; j < 3200; j += 512) {
            int e = base + j;
            if (e < EE) atomicAdd(&g_cnt[ei[EE + e]], 1);
        }
    }
}

// ---------------- CSR build ------------------------------------------------------
__global__ void k_scan()
{
    const int CH = 20;
    __shared__ int ssum[1024];
    int t = threadIdx.x;
    int base = t * CH;
    int s = 0;
    for (int k = 0; k < CH; k++) {
        int idx = base + k;
        if (idx < NN) s += g_cnt[idx];
    }
    ssum[t] = s;
    __syncthreads();
    for (int off = 1; off < 1024; off <<= 1) {
        int v = (t >= off) ? ssum[t - off] : 0;
        __syncthreads();
        ssum[t] += v;
        __syncthreads();
    }
    int run = (t > 0) ? ssum[t - 1] : 0;
    for (int k = 0; k < CH; k++) {
        int idx = base + k;
        if (idx < NN) {
            g_rowptr[idx] = run;
            g_cursor[idx] = run;
            run += g_cnt[idx];
        }
    }
    if (t == 0) g_rowptr[NN] = EE;
}

__global__ void k_fill(const int* __restrict__ ei, const float* __restrict__ ed)
{
    int e = blockIdx.x * blockDim.x + threadIdx.x;
    if (e >= EE) return;
    int dst = ei[EE + e];
    int pos = atomicAdd(&g_cursor[dst], 1);
    g_ef[pos] = make_int2(ei[e], __float_as_int(ed[e]));
}

// ---------------- atom_emb = MLP2(atom_types) : 100 -> 128 -> 128 ----------------
__global__ __launch_bounds__(256, 2) void k_atom_t(const float* __restrict__ X,
                                                   const float* __restrict__ b1,
                                                   const float* __restrict__ b2)
{
    extern __shared__ __half sm[];
    __half *Xs = sm, *Wh = sm + XROWS, *Wl = sm + XROWS + WROWS;
    int tid = threadIdx.x, wid = tid >> 5, lane = tid & 31;
    int rbase = (wid & 1) * 32, cbase = (wid >> 1) * 32;
    int row0 = blockIdx.x * TM;
    float acc[2][4][4];

    copy_w_async(0, Wh, Wl, tid);
    CP_COMMIT();
    load_xatomv(X, row0, Xs, tid);
    CP_WAIT0();
    __syncthreads();
    acc_zero(acc);
    mma_stage<7>(Xs, Wh, Wl, rbase, cbase, lane, acc);
    __syncthreads();
    epi_mid(acc, b1, false, row0, Xs, rbase, cbase, lane);
    copy_w_async(1, Wh, Wl, tid);
    CP_COMMIT(); CP_WAIT0();
    __syncthreads();
    acc_zero(acc);
    mma_stage<8>(Xs, Wh, Wl, rbase, cbase, lane, acc);
    epi_out(acc, b2, g_ae, nullptr, row0, rbase, cbase, lane, false, false);
}

// ---------------- node = relu(z@A + ae@C + TB[g]) @ fw2 + fb2 --------------------
__global__ __launch_bounds__(256, 2) void k_node_t(const float* __restrict__ Z,
                                                   const float* __restrict__ fb2)
{
    extern __shared__ __half sm[];
    __half *Xs = sm, *Wh = sm + XROWS, *Wl = sm + XROWS + WROWS;
    int tid = threadIdx.x, wid = tid >> 5, lane = tid & 31;
    int rbase = (wid & 1) * 32, cbase = (wid >> 1) * 32;
    int row0 = blockIdx.x * TM;
    float acc[2][4][4];

    copy_w_async(2, Wh, Wl, tid);
    CP_COMMIT();
    load_x128v(Z, row0, Xs, tid);
    CP_WAIT0();
    __syncthreads();
    acc_zero(acc);
    mma_stage<8>(Xs, Wh, Wl, rbase, cbase, lane, acc);
    __syncthreads();
    copy_w_async(3, Wh, Wl, tid);
    CP_COMMIT();
    load_x128v(g_ae, row0, Xs, tid);
    CP_WAIT0();
    __syncthreads();
    mma_stage<8>(Xs, Wh, Wl, rbase, cbase, lane, acc);   // += ae @ C
    __syncthreads();
    epi_mid(acc, nullptr, true, row0, Xs, rbase, cbase, lane);
    copy_w_async(4, Wh, Wl, tid);
    CP_COMMIT(); CP_WAIT0();
    __syncthreads();
    acc_zero(acc);
    mma_stage<8>(Xs, Wh, Wl, rbase, cbase, lane, acc);
    epi_out(acc, fb2, g_node, g_nf16, row0, rbase, cbase, lane, false, false);
}

// ---------------- conv MLP: Y = [relu](relu(h@W1+b1)@W2+b2) + node ---------------
__global__ __launch_bounds__(256, 2) void k_conv_t(int wsel,
                                                   const float* __restrict__ b1,
                                                   const float* __restrict__ b2,
                                                   float* __restrict__ Yext, int relu_out)
{
    extern __shared__ __half sm[];
    __half *Xs = sm, *Wh = sm + XROWS, *Wl = sm + XROWS + WROWS;
    int tid = threadIdx.x, wid = tid >> 5, lane = tid & 31;
    int rbase = (wid & 1) * 32, cbase = (wid >> 1) * 32;
    int row0 = blockIdx.x * TM;
    float* Y = Yext ? Yext : g_node;
    __half* Yf16 = Yext ? nullptr : g_nf16;
    float acc[2][4][4];

    copy_w_async(wsel, Wh, Wl, tid);
    CP_COMMIT();
    load_x128v(g_h, row0, Xs, tid);
    CP_WAIT0();
    __syncthreads();
    acc_zero(acc);
    mma_stage<8>(Xs, Wh, Wl, rbase, cbase, lane, acc);
    __syncthreads();
    epi_mid(acc, b1, false, row0, Xs, rbase, cbase, lane);
    copy_w_async(wsel + 1, Wh, Wl, tid);
    CP_COMMIT(); CP_WAIT0();
    __syncthreads();
    acc_zero(acc);
    mma_stage<8>(Xs, Wh, Wl, rbase, cbase, lane, acc);
    epi_out(acc, b2, Y, Yf16, row0, rbase, cbase, lane, relu_out != 0, true);
}

// ---------------- GINE aggregation (fp16 gather) ----------------------------------
__device__ __forceinline__ float4 ldh4(const __half* __restrict__ p)
{
    uint2 u = *(const uint2*)p;
    __half2 h01 = *(__half2*)&u.x;
    __half2 h23 = *(__half2*)&u.y;
    float2 f01 = __half22float2(h01);
    float2 f23 = __half22float2(h23);
    return make_float4(f01.x, f01.y, f23.x, f23.y);
}

__device__ __forceinline__ void agg_step(float4& acc, const float4& x, float d,
                                         const float4& v4, const float4& c4)
{
    acc.x += fmaxf(fmaf(d, v4.x, x.x + c4.x), 0.f);
    acc.y += fmaxf(fmaf(d, v4.y, x.y + c4.y), 0.f);
    acc.z += fmaxf(fmaf(d, v4.z, x.z + c4.z), 0.f);
    acc.w += fmaxf(fmaf(d, v4.w, x.w + c4.w), 0.f);
}

__global__ __launch_bounds__(256) void k_agg()
{
    int w = (blockIdx.x * blockDim.x + threadIdx.x) >> 5;
    int lane = threadIdx.x & 31;
    if (w >= NN) return;
    float4 v4 = *(const float4*)(g_v + lane * 4);
    float4 c4 = *(const float4*)(g_c + lane * 4);
    float4 acc = *(const float4*)(g_node + (size_t)w * 128 + lane * 4);
    int e = g_rowptr[w], end = g_rowptr[w + 1];
    for (; e + 8 <= end; e += 8) {
        int2 p[8];
        float4 x[8];
#pragma unroll
        for (int j = 0; j < 8; j++) p[j] = g_ef[e + j];
#pragma unroll
        for (int j = 0; j < 8; j++)
            x[j] = ldh4(g_nf16 + (size_t)p[j].x * 128 + lane * 4);
#pragma unroll
        for (int j = 0; j < 8; j++)
            agg_step(acc, x[j], __int_as_float(p[j].y), v4, c4);
    }
    for (; e < end; e++) {
        int2 p = g_ef[e];
        float4 x = ldh4(g_nf16 + (size_t)p.x * 128 + lane * 4);
        agg_step(acc, x, __int_as_float(p.y), v4, c4);
    }
    *(float4*)(g_h + (size_t)w * 128 + lane * 4) = acc;
}

// ---------------- launch ---------------------------------------------------------
extern "C" void kernel_launch(void* const* d_in, const int* in_sizes, int n_in,
                              void* d_out, int out_size)
{
    const float* z   = (const float*)d_in[0];
    const float* t   = (const float*)d_in[1];
    const float* at  = (const float*)d_in[2];
    const float* ed  = (const float*)d_in[3];
    const int*   ei  = (const int*)d_in[4];
    const int*   na  = (const int*)d_in[5];
    const float* nw1 = (const float*)d_in[6];
    const float* nb1 = (const float*)d_in[7];
    const float* nw2 = (const float*)d_in[8];
    const float* nb2 = (const float*)d_in[9];
    const float* tw1 = (const float*)d_in[10];
    const float* tb1 = (const float*)d_in[11];
    const float* tw2 = (const float*)d_in[12];
    const float* tb2 = (const float*)d_in[13];
    const float* ew1 = (const float*)d_in[14];
    const float* eb1 = (const float*)d_in[15];
    const float* ew2 = (const float*)d_in[16];
    const float* eb2 = (const float*)d_in[17];
    const float* fw1 = (const float*)d_in[18];
    const float* fb1 = (const float*)d_in[19];
    const float* fw2 = (const float*)d_in[20];
    const float* fb2 = (const float*)d_in[21];
    const float* cw1 = (const float*)d_in[22];
    const float* cb1 = (const float*)d_in[23];
    const float* cw2 = (const float*)d_in[24];
    const float* cb2 = (const float*)d_in[25];
    float* out = (float*)d_out;

    cudaFuncSetAttribute(k_atom_t, cudaFuncAttributeMaxDynamicSharedMemorySize, SMEM_MMA);
    cudaFuncSetAttribute(k_node_t, cudaFuncAttributeMaxDynamicSharedMemorySize, SMEM_MMA);
    cudaFuncSetAttribute(k_conv_t, cudaFuncAttributeMaxDynamicSharedMemorySize, SMEM_MMA);

    k_setup<<<(NN + 511) / 512, 512>>>(ew1, eb1, ew2, eb2, na);
    k_mega<<<MEGA_GRID, 512>>>(t, tw1, tb1, tw2, tb2, fw1, fb1, ei,
                               nw1, nw2, fw1, fw1 + 256 * 128, fw2,
                               cw1, cw2, cw1 + 16384, cw2 + 16384,
                               cw1 + 2 * 16384, cw2 + 2 * 16384);
    k_scan<<<1, 1024>>>();
    k_fill<<<(EE + 511) / 512, 512>>>(ei, ed);
    k_atom_t<<<NT64, 256, SMEM_MMA>>>(at, nb1, nb2);
    k_node_t<<<NT64, 256, SMEM_MMA>>>(z, fb2);

    for (int i = 0; i < 3; i++) {
        k_agg<<<(NN * 32 + 255) / 256, 256>>>();
        float* Yext = (i == 2) ? out : nullptr;
        k_conv_t<<<NT64, 256, SMEM_MMA>>>(5 + i * 2, cb1 + i * 128, cb2 + i * 128,
                                          Yext, (i < 2) ? 1 : 0);
    }
}